// round 13
// baseline (speedup 1.0000x reference)
#include <cuda_runtime.h>
#include <cuda_bf16.h>
#include <math.h>
#include <stdint.h>

// Problem constants
#define NBATCH 2
#define L_SEQ 2048
#define D_MODEL 1024
#define H_HEADS 16
#define DH 64
#define QKV_STRIDE 3072
#define NH_TOT (NBATCH * H_HEADS)
#define OUT_ELEMS (NBATCH * L_SEQ * D_MODEL)
#define GK 1024
#define GKC 32
// gemm smem: 3 stages x (A 128 rows + B 256 rows) x 2 mats x 80B
#define ROW_B 80
#define SA_B (128 * ROW_B)
#define SB_B (256 * ROW_B)
#define STG_B (2 * SA_B + 2 * SB_B)
#define GT_SMEM (3 * STG_B)

#define VROW 144

// Static device scratch
__device__ float g_qkv[(size_t)NBATCH * L_SEQ * QKV_STRIDE];
__device__ float g_cpart[NH_TOT * 16 * DH];
__device__ __align__(16) __nv_bfloat16 g_ah[(size_t)4096 * 1024];
__device__ __align__(16) __nv_bfloat16 g_al[(size_t)4096 * 1024];
__device__ __align__(16) __nv_bfloat16 g_bh[(size_t)3072 * 1024];
__device__ __align__(16) __nv_bfloat16 g_bl[(size_t)3072 * 1024];
__device__ __align__(16) __nv_bfloat16 g_vh[(size_t)4096 * 1024];
__device__ __align__(16) __nv_bfloat16 g_vl[(size_t)4096 * 1024];
__device__ __align__(16) __nv_bfloat16 g_wnh[NH_TOT * L_SEQ];
__device__ __align__(16) __nv_bfloat16 g_wnl[NH_TOT * L_SEQ];

// ---------------------------------------------------------------------------
__device__ __forceinline__ uint32_t smem_u32(const void* p) {
    uint32_t a;
    asm("{ .reg .u64 t; cvta.to.shared.u64 t, %1; cvt.u32.u64 %0, t; }" : "=r"(a) : "l"(p));
    return a;
}

#define CP_ASYNC16(dst, src) \
    asm volatile("cp.async.cg.shared.global [%0], [%1], 16;" :: "r"(dst), "l"(src))
#define CP_COMMIT() asm volatile("cp.async.commit_group;" ::: "memory")
#define CP_WAIT1()  asm volatile("cp.async.wait_group 1;" ::: "memory")
#define CP_WAIT0()  asm volatile("cp.async.wait_group 0;" ::: "memory")

#define LDSM_X4(r, addr) \
    asm volatile("ldmatrix.sync.aligned.m8n8.x4.shared.b16 {%0,%1,%2,%3}, [%4];" \
        : "=r"((r)[0]), "=r"((r)[1]), "=r"((r)[2]), "=r"((r)[3]) : "r"(addr))

#define LDSM_X4_T(r, addr) \
    asm volatile("ldmatrix.sync.aligned.m8n8.x4.trans.shared.b16 {%0,%1,%2,%3}, [%4];" \
        : "=r"((r)[0]), "=r"((r)[1]), "=r"((r)[2]), "=r"((r)[3]) : "r"(addr))

#define MMA_BF16(d, a, b0, b1) \
    asm volatile("mma.sync.aligned.m16n8k16.row.col.f32.bf16.bf16.f32 " \
        "{%0,%1,%2,%3}, {%4,%5,%6,%7}, {%8,%9}, {%0,%1,%2,%3};" \
        : "+f"((d)[0]), "+f"((d)[1]), "+f"((d)[2]), "+f"((d)[3]) \
        : "r"((a)[0]), "r"((a)[1]), "r"((a)[2]), "r"((a)[3]), "r"(b0), "r"(b1))

__device__ __forceinline__ uint32_t bfpack(float a, float b) {
    __nv_bfloat16 ha = __float2bfloat16(a), hb = __float2bfloat16(b);
    return (uint32_t)__bfloat16_as_ushort(ha) | ((uint32_t)__bfloat16_as_ushort(hb) << 16);
}

// ---------------------------------------------------------------------------
// Split fp32 -> (bf16 hi, bf16 lo)
// ---------------------------------------------------------------------------
__global__ __launch_bounds__(256)
void split_bf16_kernel(const float4* __restrict__ src, uint2* __restrict__ hi,
                       uint2* __restrict__ lo, int n4)
{
    int i = blockIdx.x * blockDim.x + threadIdx.x;
    if (i >= n4) return;
    float4 v = src[i];
    __nv_bfloat16 hx = __float2bfloat16(v.x), hy = __float2bfloat16(v.y);
    __nv_bfloat16 hz = __float2bfloat16(v.z), hw = __float2bfloat16(v.w);
    uint2 h, l;
    h.x = (uint32_t)__bfloat16_as_ushort(hx) | ((uint32_t)__bfloat16_as_ushort(hy) << 16);
    h.y = (uint32_t)__bfloat16_as_ushort(hz) | ((uint32_t)__bfloat16_as_ushort(hw) << 16);
    l.x = bfpack(v.x - __bfloat162float(hx), v.y - __bfloat162float(hy));
    l.y = bfpack(v.z - __bfloat162float(hz), v.w - __bfloat162float(hw));
    hi[i] = h;
    lo[i] = l;
}

// ---------------------------------------------------------------------------
// HMMA GEMM v3 (proven R8): CTA tile 128x256, 8 warps, warp tile 64x64.
// ---------------------------------------------------------------------------
__global__ __launch_bounds__(256, 1)
void gemm_mma_kernel(const __nv_bfloat16* __restrict__ Ah, const __nv_bfloat16* __restrict__ Al,
                     const __nv_bfloat16* __restrict__ Bh, const __nv_bfloat16* __restrict__ Bl,
                     const float* __restrict__ bias, float* __restrict__ C,
                     __nv_bfloat16* __restrict__ Vh, __nv_bfloat16* __restrict__ Vl, int N)
{
    extern __shared__ __align__(128) char smem[];
    const uint32_t sbase = smem_u32(smem);
    const int tid = threadIdx.x;
    const int lane = tid & 31, wid = tid >> 5;
    const int wm = wid >> 2, wn = wid & 3;
    const int bm = blockIdx.y << 7, bn = blockIdx.x << 8;

    auto load_stage = [&](int kc, int st_idx) {
        const uint32_t st = sbase + (uint32_t)st_idx * STG_B;
        const int koff = kc << 5;
#pragma unroll
        for (int i = 0; i < 4; i++) {
            const int idx = tid + (i << 8);
            const int mat = idx >> 9;
            const int row = (idx >> 2) & 127;
            const int c = idx & 3;
            const uint32_t so = (uint32_t)(mat * SA_B + row * ROW_B + c * 16);
            const __nv_bfloat16* src = (mat ? Al : Ah) + (size_t)(bm + row) * GK + koff + (c << 3);
            CP_ASYNC16(st + so, src);
        }
#pragma unroll
        for (int i = 0; i < 8; i++) {
            const int idx = tid + (i << 8);
            const int mat = idx >> 10;
            const int row = (idx >> 2) & 255;
            const int c = idx & 3;
            const uint32_t so = (uint32_t)(2 * SA_B + mat * SB_B + row * ROW_B + c * 16);
            const __nv_bfloat16* src = (mat ? Bl : Bh) + (size_t)(bn + row) * GK + koff + (c << 3);
            CP_ASYNC16(st + so, src);
        }
    };

    uint32_t aoff[4], boff[4];
#pragma unroll
    for (int mt = 0; mt < 4; mt++)
        aoff[mt] = (uint32_t)((wm * 64 + mt * 16 + (lane & 15)) * ROW_B + (lane >> 4) * 16);
#pragma unroll
    for (int gg = 0; gg < 4; gg++)
        boff[gg] = (uint32_t)((wn * 64 + gg * 16 + ((lane >> 4) & 1) * 8 + (lane & 7)) * ROW_B
                              + ((lane >> 3) & 1) * 16);

    float acc[4][8][4];
#pragma unroll
    for (int i = 0; i < 4; i++)
#pragma unroll
        for (int j = 0; j < 8; j++)
#pragma unroll
            for (int r = 0; r < 4; r++) acc[i][j][r] = 0.f;

    load_stage(0, 0); CP_COMMIT();
    load_stage(1, 1); CP_COMMIT();

    int s = 0;
    for (int kc = 0; kc < GKC; kc++) {
        CP_WAIT1();
        __syncthreads();
        if (kc + 2 < GKC) load_stage(kc + 2, (kc + 2) % 3);
        CP_COMMIT();

        const uint32_t st = sbase + (uint32_t)s * STG_B;
#pragma unroll
        for (int ks = 0; ks < 2; ks++) {
            const uint32_t ko = (uint32_t)(ks * 32);
            uint32_t ah[4][4], al[4][4];
#pragma unroll
            for (int mt = 0; mt < 4; mt++) {
                LDSM_X4(ah[mt], st + aoff[mt] + ko);
                LDSM_X4(al[mt], st + SA_B + aoff[mt] + ko);
            }
#pragma unroll
            for (int gg = 0; gg < 4; gg++) {
                uint32_t bh4[4], bl4[4];
                LDSM_X4(bh4, st + 2 * SA_B + boff[gg] + ko);
                LDSM_X4(bl4, st + 2 * SA_B + SB_B + boff[gg] + ko);
#pragma unroll
                for (int mt = 0; mt < 4; mt++) {
                    MMA_BF16(acc[mt][gg * 2],     ah[mt], bh4[0], bh4[1]);
                    MMA_BF16(acc[mt][gg * 2 + 1], ah[mt], bh4[2], bh4[3]);
                }
#pragma unroll
                for (int mt = 0; mt < 4; mt++) {
                    MMA_BF16(acc[mt][gg * 2],     ah[mt], bl4[0], bl4[1]);
                    MMA_BF16(acc[mt][gg * 2 + 1], ah[mt], bl4[2], bl4[3]);
                }
#pragma unroll
                for (int mt = 0; mt < 4; mt++) {
                    MMA_BF16(acc[mt][gg * 2],     al[mt], bh4[0], bh4[1]);
                    MMA_BF16(acc[mt][gg * 2 + 1], al[mt], bh4[2], bh4[3]);
                }
            }
        }
        s++; if (s == 3) s = 0;
    }

    const bool vsplit = (Vh != nullptr) && (bn >= 2048);
#pragma unroll
    for (int mt = 0; mt < 4; mt++) {
        const int r0 = bm + wm * 64 + mt * 16 + (lane >> 2);
#pragma unroll
        for (int j = 0; j < 8; j++) {
            const int colg = bn + wn * 64 + (j >> 1) * 16 + (j & 1) * 8 + (lane & 3) * 2;
            const float b0 = bias[colg], b1 = bias[colg + 1];
            const float v00 = acc[mt][j][0] + b0, v01 = acc[mt][j][1] + b1;
            const float v10 = acc[mt][j][2] + b0, v11 = acc[mt][j][3] + b1;
            if (!vsplit) {
                *(float2*)(C + (size_t)r0 * N + colg) = make_float2(v00, v01);
                *(float2*)(C + (size_t)(r0 + 8) * N + colg) = make_float2(v10, v11);
            } else {
                const int cv = colg - 2048;
                uint32_t* vh32 = (uint32_t*)Vh;
                uint32_t* vl32 = (uint32_t*)Vl;
                {
                    __nv_bfloat16 h0 = __float2bfloat16(v00), h1 = __float2bfloat16(v01);
                    uint32_t ph = (uint32_t)__bfloat16_as_ushort(h0) |
                                  ((uint32_t)__bfloat16_as_ushort(h1) << 16);
                    uint32_t pl = bfpack(v00 - __bfloat162float(h0), v01 - __bfloat162float(h1));
                    vh32[((size_t)r0 * 1024 + cv) >> 1] = ph;
                    vl32[((size_t)r0 * 1024 + cv) >> 1] = pl;
                }
                {
                    __nv_bfloat16 h0 = __float2bfloat16(v10), h1 = __float2bfloat16(v11);
                    uint32_t ph = (uint32_t)__bfloat16_as_ushort(h0) |
                                  ((uint32_t)__bfloat16_as_ushort(h1) << 16);
                    uint32_t pl = bfpack(v10 - __bfloat162float(h0), v11 - __bfloat162float(h1));
                    vh32[((size_t)(r0 + 8) * 1024 + cv) >> 1] = ph;
                    vl32[((size_t)(r0 + 8) * 1024 + cv) >> 1] = pl;
                }
            }
        }
    }
}

// ---------------------------------------------------------------------------
// conv -> GELU -> LN -> partial mean over a 128-t chunk. Grid (16, 32).
// (R8 3-load body — measured faster than sliding window.)
// ---------------------------------------------------------------------------
__global__ __launch_bounds__(256)
void conv_part_kernel(const float* __restrict__ conv_w, const float* __restrict__ conv_b,
                      const float* __restrict__ ln_g, const float* __restrict__ ln_b)
{
    const int chunk = blockIdx.x;
    const int nh = blockIdx.y;
    const int n = nh >> 4, h = nh & 15;
    const int tid = threadIdx.x;
    const int w = tid >> 5, lane = tid & 31;
    const int d0 = lane, d1 = lane + 32;
    const float* qbase = g_qkv + (size_t)n * L_SEQ * QKV_STRIDE + h * DH;

    const float cw00 = conv_w[d0 * 3 + 0], cw01 = conv_w[d0 * 3 + 1], cw02 = conv_w[d0 * 3 + 2];
    const float cw10 = conv_w[d1 * 3 + 0], cw11 = conv_w[d1 * 3 + 1], cw12 = conv_w[d1 * 3 + 2];
    const float cb0 = conv_b[d0], cb1 = conv_b[d1];
    const float lg0 = ln_g[d0], lb0 = ln_b[d0];
    const float lg1 = ln_g[d1], lb1 = ln_b[d1];

    float p0 = 0.f, p1 = 0.f;
#pragma unroll 4
    for (int i = 0; i < 16; i++) {
        const int t = chunk * 128 + (w << 4) + i;
        float c0 = cb0, c1 = cb1;
        {
            const float* r = qbase + (size_t)t * QKV_STRIDE;
            c0 = fmaf(r[d0], cw02, c0); c1 = fmaf(r[d1], cw12, c1);
        }
        if (t >= 1) {
            const float* r = qbase + (size_t)(t - 1) * QKV_STRIDE;
            c0 = fmaf(r[d0], cw01, c0); c1 = fmaf(r[d1], cw11, c1);
        }
        if (t >= 2) {
            const float* r = qbase + (size_t)(t - 2) * QKV_STRIDE;
            c0 = fmaf(r[d0], cw00, c0); c1 = fmaf(r[d1], cw10, c1);
        }
        float g0 = 0.5f * c0 * (1.f + erff(c0 * 0.70710678118654752f));
        float g1 = 0.5f * c1 * (1.f + erff(c1 * 0.70710678118654752f));
        float sv = g0 + g1, sq = g0 * g0 + g1 * g1;
#pragma unroll
        for (int o = 16; o; o >>= 1) {
            sv += __shfl_xor_sync(0xffffffffu, sv, o);
            sq += __shfl_xor_sync(0xffffffffu, sq, o);
        }
        float mu = sv * (1.f / 64.f);
        float var = sq * (1.f / 64.f) - mu * mu;
        float rs = rsqrtf(var + 1e-5f);
        p0 += (g0 - mu) * rs * lg0 + lb0;
        p1 += (g1 - mu) * rs * lg1 + lb1;
    }

    __shared__ float part[8][64];
    part[w][d0] = p0;
    part[w][d1] = p1;
    __syncthreads();
    if (tid < 64) {
        float sv = 0.f;
#pragma unroll
        for (int i = 0; i < 8; i++) sv += part[i][tid];
        g_cpart[(nh * 16 + chunk) * 64 + tid] = sv;
    }
}

// ---------------------------------------------------------------------------
// Reduce conv partials -> q_rel -> Wk -> L1 norm -> Wn bf16 split. (merged)
// ---------------------------------------------------------------------------
__global__ __launch_bounds__(256)
void wk_kernel()
{
    const int nh = blockIdx.x;
    const int n = nh >> 4, h = nh & 15;
    const int tid = threadIdx.x;
    __shared__ float4 qs4[16];
    if (tid < 64) {
        float sv = 0.f;
#pragma unroll
        for (int i = 0; i < 16; i++) sv += g_cpart[(nh * 16 + i) * 64 + tid];
        ((float*)qs4)[tid] = sv * (0.125f / 2048.f);
    }
    __syncthreads();

    const float* kbase = g_qkv + (size_t)n * L_SEQ * QKV_STRIDE + D_MODEL + h * DH;
    float wk[8];
    float la = 0.f;
#pragma unroll
    for (int i = 0; i < 8; i++) {
        int l = tid + i * 256;
        const float4* kr = (const float4*)(kbase + (size_t)l * QKV_STRIDE);
        float a = 0.f;
#pragma unroll
        for (int d4 = 0; d4 < 16; d4++) {
            float4 kv = kr[d4]; float4 q = qs4[d4];
            a = fmaf(q.x, kv.x, a); a = fmaf(q.y, kv.y, a);
            a = fmaf(q.z, kv.z, a); a = fmaf(q.w, kv.w, a);
        }
        wk[i] = a;
        la += fabsf(a);
    }
    __shared__ float red[256];
    red[tid] = la;
    __syncthreads();
    for (int o = 128; o; o >>= 1) {
        if (tid < o) red[tid] += red[tid + o];
        __syncthreads();
    }
    const float scale = 1.f / (red[0] + 1e-6f);
#pragma unroll
    for (int i = 0; i < 8; i++) {
        const float wv = wk[i] * scale;
        __nv_bfloat16 hh = __float2bfloat16(wv);
        g_wnh[nh * L_SEQ + tid + i * 256] = hh;
        g_wnl[nh * L_SEQ + tid + i * 256] = __float2bfloat16(wv - __bfloat162float(hh));
    }
}

// ---------------------------------------------------------------------------
// Toeplitz attention via HMMA v4 (R12) + 2 CTAs/SM via launch_bounds.
// 8 warps x 32 t-rows (2 m-tiles each), 256 t-rows per CTA, double-buffered
// cp.async, heavy-first, per-warp diagonal skip.
// ---------------------------------------------------------------------------
__global__ __launch_bounds__(256, 2)
void attn_mma_kernel()
{
    const int bid = blockIdx.x;
    const int g8 = 7 - (bid >> 5);
    const int nh = bid & 31;
    const int n = nh >> 4, h = nh & 15;
    const int tid = threadIdx.x;
    const int lane = tid & 31, w = tid >> 5;
    const int t_base = g8 << 8;
    const int C = 4 * g8 + 4;

    __shared__ __align__(16) char vsm[2][2][64 * VROW];
    __shared__ __nv_bfloat16 wseg[2][2][320];

    const uint32_t vbase = smem_u32(vsm);
    const __nv_bfloat16* wnh = g_wnh + nh * L_SEQ;
    const __nv_bfloat16* wnl = g_wnl + nh * L_SEQ;
    const __nv_bfloat16 zero = __float2bfloat16(0.f);

    auto load_w = [&](int c, int buf) {
        const int base = t_base - (c << 6) - 63;
        {
            const int j = tid;
            const int lag = base + j;
            wseg[buf][0][j] = (lag >= 0) ? wnh[lag] : zero;
            wseg[buf][1][j] = (lag >= 0) ? wnl[lag] : zero;
        }
        if (tid < 64) {
            const int j = 256 + tid;
            const int lag = base + j;
            wseg[buf][0][j] = (lag >= 0) ? wnh[lag] : zero;
            wseg[buf][1][j] = (lag >= 0) ? wnl[lag] : zero;
        }
    };
    auto load_v = [&](int c, int buf) {
        const uint32_t vb = vbase + (uint32_t)buf * (2 * 64 * VROW);
#pragma unroll
        for (int i = 0; i < 2; i++) {
            const int idx = tid + (i << 8);
            const int row = idx >> 3, ch = idx & 7;
            const size_t ga = (size_t)(n * L_SEQ + (c << 6) + row) * 1024 + h * DH + (ch << 3);
            const uint32_t so = (uint32_t)(row * VROW + (ch << 4));
            CP_ASYNC16(vb + so,             g_vh + ga);
            CP_ASYNC16(vb + so + 64 * VROW, g_vl + ga);
        }
    };

    float acc[2][8][4];
#pragma unroll
    for (int m = 0; m < 2; m++)
#pragma unroll
        for (int i = 0; i < 8; i++)
#pragma unroll
            for (int j = 0; j < 4; j++) acc[m][i][j] = 0.f;

    load_w(0, 0); load_v(0, 0); CP_COMMIT();

    const int r0 = lane >> 2;
    const int c0 = (lane & 3) << 1;
    const uint32_t lrow = (uint32_t)(lane & 15);
    const uint32_t lcol = (uint32_t)((lane >> 4) << 4);

    for (int c = 0; c < C; c++) {
        const int buf = c & 1;
        if (c + 1 < C) {
            load_w(c + 1, buf ^ 1);
            load_v(c + 1, buf ^ 1);
            CP_COMMIT();
            CP_WAIT1();
        } else {
            CP_WAIT0();
        }
        __syncthreads();

        if (t_base + (w << 5) + 31 >= (c << 6)) {
            const __nv_bfloat16* wh = wseg[buf][0];
            const __nv_bfloat16* wl = wseg[buf][1];
            const uint32_t vh_s = vbase + (uint32_t)buf * (2 * 64 * VROW);
            const uint32_t vl_s = vh_s + 64 * VROW;

#pragma unroll
            for (int ks = 0; ks < 4; ks++) {
                const int jbw = 63 + (w << 5) + r0 - (ks << 4) - c0;
                uint32_t hA = (uint32_t)__bfloat16_as_ushort(wh[jbw - 8]) |
                              ((uint32_t)__bfloat16_as_ushort(wh[jbw - 9]) << 16);
                uint32_t hB = (uint32_t)__bfloat16_as_ushort(wh[jbw]) |
                              ((uint32_t)__bfloat16_as_ushort(wh[jbw - 1]) << 16);
                uint32_t hCq = (uint32_t)__bfloat16_as_ushort(wh[jbw + 8]) |
                              ((uint32_t)__bfloat16_as_ushort(wh[jbw + 7]) << 16);
                uint32_t hD = (uint32_t)__bfloat16_as_ushort(wh[jbw + 16]) |
                              ((uint32_t)__bfloat16_as_ushort(wh[jbw + 15]) << 16);
                uint32_t hE = (uint32_t)__bfloat16_as_ushort(wh[jbw + 24]) |
                              ((uint32_t)__bfloat16_as_ushort(wh[jbw + 23]) << 16);
                uint32_t lA = (uint32_t)__bfloat16_as_ushort(wl[jbw - 8]) |
                              ((uint32_t)__bfloat16_as_ushort(wl[jbw - 9]) << 16);
                uint32_t lB = (uint32_t)__bfloat16_as_ushort(wl[jbw]) |
                              ((uint32_t)__bfloat16_as_ushort(wl[jbw - 1]) << 16);
                uint32_t lCq = (uint32_t)__bfloat16_as_ushort(wl[jbw + 8]) |
                              ((uint32_t)__bfloat16_as_ushort(wl[jbw + 7]) << 16);
                uint32_t lD = (uint32_t)__bfloat16_as_ushort(wl[jbw + 16]) |
                              ((uint32_t)__bfloat16_as_ushort(wl[jbw + 15]) << 16);
                uint32_t lE = (uint32_t)__bfloat16_as_ushort(wl[jbw + 24]) |
                              ((uint32_t)__bfloat16_as_ushort(wl[jbw + 23]) << 16);
                uint32_t a0h[4] = {hB, hCq, hA, hB};
                uint32_t a1h[4] = {hD, hE, hCq, hD};
                uint32_t a0l[4] = {lB, lCq, lA, lB};
                uint32_t a1l[4] = {lD, lE, lCq, lD};

                const uint32_t radd = (uint32_t)((ks * 16 + lrow) * VROW) + lcol;
#pragma unroll
                for (int gg = 0; gg < 4; gg++) {
                    uint32_t bh4[4], bl4[4];
                    const uint32_t ga = radd + (uint32_t)(gg << 5);
                    LDSM_X4_T(bh4, vh_s + ga);
                    LDSM_X4_T(bl4, vl_s + ga);
                    MMA_BF16(acc[0][gg * 2],     a0h, bh4[0], bh4[1]);
                    MMA_BF16(acc[0][gg * 2 + 1], a0h, bh4[2], bh4[3]);
                    MMA_BF16(acc[1][gg * 2],     a1h, bh4[0], bh4[1]);
                    MMA_BF16(acc[1][gg * 2 + 1], a1h, bh4[2], bh4[3]);
                    MMA_BF16(acc[0][gg * 2],     a0h, bl4[0], bl4[1]);
                    MMA_BF16(acc[0][gg * 2 + 1], a0h, bl4[2], bl4[3]);
                    MMA_BF16(acc[1][gg * 2],     a1h, bl4[0], bl4[1]);
                    MMA_BF16(acc[1][gg * 2 + 1], a1h, bl4[2], bl4[3]);
                    MMA_BF16(acc[0][gg * 2],     a0l, bh4[0], bh4[1]);
                    MMA_BF16(acc[0][gg * 2 + 1], a0l, bh4[2], bh4[3]);
                    MMA_BF16(acc[1][gg * 2],     a1l, bh4[0], bh4[1]);
                    MMA_BF16(acc[1][gg * 2 + 1], a1l, bh4[2], bh4[3]);
                }
            }
        }
        __syncthreads();
    }

    uint32_t* mh32 = (uint32_t*)g_ah;
    uint32_t* ml32 = (uint32_t*)g_al;
#pragma unroll
    for (int mt = 0; mt < 2; mt++) {
        const size_t rA = (size_t)(n * L_SEQ + t_base + (w << 5) + (mt << 4) + r0);
#pragma unroll
        for (int nb = 0; nb < 8; nb++) {
            const int col = h * DH + nb * 8 + c0;
            {
                float v0 = acc[mt][nb][0], v1 = acc[mt][nb][1];
                __nv_bfloat16 h0 = __float2bfloat16(v0), h1 = __float2bfloat16(v1);
                uint32_t ph = (uint32_t)__bfloat16_as_ushort(h0) |
                              ((uint32_t)__bfloat16_as_ushort(h1) << 16);
                uint32_t pl = bfpack(v0 - __bfloat162float(h0), v1 - __bfloat162float(h1));
                mh32[(rA * 1024 + col) >> 1] = ph;
                ml32[(rA * 1024 + col) >> 1] = pl;
            }
            {
                float v0 = acc[mt][nb][2], v1 = acc[mt][nb][3];
                __nv_bfloat16 h0 = __float2bfloat16(v0), h1 = __float2bfloat16(v1);
                uint32_t ph = (uint32_t)__bfloat16_as_ushort(h0) |
                              ((uint32_t)__bfloat16_as_ushort(h1) << 16);
                uint32_t pl = bfpack(v0 - __bfloat162float(h0), v1 - __bfloat162float(h1));
                mh32[((rA + 8) * 1024 + col) >> 1] = ph;
                ml32[((rA + 8) * 1024 + col) >> 1] = pl;
            }
        }
    }
}

__global__ void fill_kernel(float* p, int nfill, float v)
{
    int i = blockIdx.x * blockDim.x + threadIdx.x;
    if (i < nfill) p[i] = v;
}

// ---------------------------------------------------------------------------
extern "C" void kernel_launch(void* const* d_in, const int* in_sizes, int n_in,
                              void* d_out, int out_size)
{
    const float* x      = (const float*)d_in[0];
    const float* in_w   = (const float*)d_in[1];
    const float* in_b   = (const float*)d_in[2];
    const float* conv_w = (const float*)d_in[3];
    const float* conv_b = (const float*)d_in[4];
    const float* ln_g   = (const float*)d_in[5];
    const float* ln_b   = (const float*)d_in[6];
    const float* out_w  = (const float*)d_in[7];
    const float* out_b  = (const float*)d_in[8];
    float* out = (float*)d_out;

    void* p;
    cudaGetSymbolAddress(&p, g_qkv);    float* qkv = (float*)p;
    cudaGetSymbolAddress(&p, g_ah);     __nv_bfloat16* ah = (__nv_bfloat16*)p;
    cudaGetSymbolAddress(&p, g_al);     __nv_bfloat16* al = (__nv_bfloat16*)p;
    cudaGetSymbolAddress(&p, g_bh);     __nv_bfloat16* bh = (__nv_bfloat16*)p;
    cudaGetSymbolAddress(&p, g_bl);     __nv_bfloat16* bl = (__nv_bfloat16*)p;
    cudaGetSymbolAddress(&p, g_vh);     __nv_bfloat16* vh = (__nv_bfloat16*)p;
    cudaGetSymbolAddress(&p, g_vl);     __nv_bfloat16* vl = (__nv_bfloat16*)p;

    cudaFuncSetAttribute(gemm_mma_kernel, cudaFuncAttributeMaxDynamicSharedMemorySize, GT_SMEM);

    // splits for GEMM1
    split_bf16_kernel<<<4096, 256>>>((const float4*)x, (uint2*)ah, (uint2*)al, 4096 * 1024 / 4);
    split_bf16_kernel<<<3072, 256>>>((const float4*)in_w, (uint2*)bh, (uint2*)bl, 3072 * 1024 / 4);

    // GEMM1 (merged): q,k cols -> qkv fp32; V cols -> bf16 hi/lo split (fused)
    gemm_mma_kernel<<<dim3(12, 32), 256, GT_SMEM>>>(ah, al, bh, bl, in_b, qkv, vh, vl, QKV_STRIDE);

    // conv -> gelu -> LN -> partial mean
    conv_part_kernel<<<dim3(16, NH_TOT), 256>>>(conv_w, conv_b, ln_g, ln_b);

    // reduce + Wk -> Wn (bf16 split), merged
    wk_kernel<<<NH_TOT, 256>>>();

    // causal Toeplitz attention (HMMA, 8 warps / 256 t-rows per CTA, 2 CTA/SM)
    attn_mma_kernel<<<256, 256>>>();

    // GEMM2: out = merged @ out_w^T + out_b
    split_bf16_kernel<<<1024, 256>>>((const float4*)out_w, (uint2*)bh, (uint2*)bl, 1024 * 1024 / 4);
    gemm_mma_kernel<<<dim3(4, 32), 256, GT_SMEM>>>(ah, al, bh, bl, out_b, out,
                                                   nullptr, nullptr, D_MODEL);

    // mock attention weights
    int nmock = out_size - OUT_ELEMS;
    if (nmock > 0)
        fill_kernel<<<(nmock + 255) / 256, 256>>>(out + OUT_ELEMS, nmock, 1.0f / (float)L_SEQ);
}

// round 14
// speedup vs baseline: 1.0595x; 1.0595x over previous
#include <cuda_runtime.h>
#include <cuda_bf16.h>
#include <math.h>
#include <stdint.h>

// Problem constants
#define NBATCH 2
#define L_SEQ 2048
#define D_MODEL 1024
#define H_HEADS 16
#define DH 64
#define QKV_STRIDE 3072
#define NH_TOT (NBATCH * H_HEADS)
#define OUT_ELEMS (NBATCH * L_SEQ * D_MODEL)
#define GK 1024
#define GKC 32
// gemm smem: 3 stages x (A 128 rows + B 256 rows) x 2 mats x 80B
#define ROW_B 80
#define SA_B (128 * ROW_B)
#define SB_B (256 * ROW_B)
#define STG_B (2 * SA_B + 2 * SB_B)
#define GT_SMEM (3 * STG_B)

#define VROW 144

// Static device scratch
__device__ float g_qkv[(size_t)NBATCH * L_SEQ * QKV_STRIDE];
__device__ float g_cpart[NH_TOT * 16 * DH];
__device__ __align__(16) __nv_bfloat16 g_ah[(size_t)4096 * 1024];
__device__ __align__(16) __nv_bfloat16 g_al[(size_t)4096 * 1024];
__device__ __align__(16) __nv_bfloat16 g_bh[(size_t)3072 * 1024];
__device__ __align__(16) __nv_bfloat16 g_bl[(size_t)3072 * 1024];
__device__ __align__(16) __nv_bfloat16 g_vh[(size_t)4096 * 1024];
__device__ __align__(16) __nv_bfloat16 g_vl[(size_t)4096 * 1024];
__device__ __align__(16) __nv_bfloat16 g_wnh[NH_TOT * L_SEQ];
__device__ __align__(16) __nv_bfloat16 g_wnl[NH_TOT * L_SEQ];

// ---------------------------------------------------------------------------
__device__ __forceinline__ uint32_t smem_u32(const void* p) {
    uint32_t a;
    asm("{ .reg .u64 t; cvta.to.shared.u64 t, %1; cvt.u32.u64 %0, t; }" : "=r"(a) : "l"(p));
    return a;
}

#define CP_ASYNC16(dst, src) \
    asm volatile("cp.async.cg.shared.global [%0], [%1], 16;" :: "r"(dst), "l"(src))
#define CP_COMMIT() asm volatile("cp.async.commit_group;" ::: "memory")
#define CP_WAIT1()  asm volatile("cp.async.wait_group 1;" ::: "memory")
#define CP_WAIT0()  asm volatile("cp.async.wait_group 0;" ::: "memory")

#define LDSM_X4(r, addr) \
    asm volatile("ldmatrix.sync.aligned.m8n8.x4.shared.b16 {%0,%1,%2,%3}, [%4];" \
        : "=r"((r)[0]), "=r"((r)[1]), "=r"((r)[2]), "=r"((r)[3]) : "r"(addr))

#define LDSM_X4_T(r, addr) \
    asm volatile("ldmatrix.sync.aligned.m8n8.x4.trans.shared.b16 {%0,%1,%2,%3}, [%4];" \
        : "=r"((r)[0]), "=r"((r)[1]), "=r"((r)[2]), "=r"((r)[3]) : "r"(addr))

#define MMA_BF16(d, a, b0, b1) \
    asm volatile("mma.sync.aligned.m16n8k16.row.col.f32.bf16.bf16.f32 " \
        "{%0,%1,%2,%3}, {%4,%5,%6,%7}, {%8,%9}, {%0,%1,%2,%3};" \
        : "+f"((d)[0]), "+f"((d)[1]), "+f"((d)[2]), "+f"((d)[3]) \
        : "r"((a)[0]), "r"((a)[1]), "r"((a)[2]), "r"((a)[3]), "r"(b0), "r"(b1))

__device__ __forceinline__ uint32_t bfpack(float a, float b) {
    __nv_bfloat16 ha = __float2bfloat16(a), hb = __float2bfloat16(b);
    return (uint32_t)__bfloat16_as_ushort(ha) | ((uint32_t)__bfloat16_as_ushort(hb) << 16);
}

// ---------------------------------------------------------------------------
// Split fp32 -> (bf16 hi, bf16 lo). 2 independent float4s per thread (MLP=2).
// n4 must be even multiple of 256 (true for all call sites).
// ---------------------------------------------------------------------------
__global__ __launch_bounds__(256)
void split_bf16_kernel(const float4* __restrict__ src, uint2* __restrict__ hi,
                       uint2* __restrict__ lo, int n4)
{
    const int half = n4 >> 1;
    const int i0 = blockIdx.x * blockDim.x + threadIdx.x;
    if (i0 >= half) return;
    const int i1 = i0 + half;
    float4 v0 = src[i0];
    float4 v1 = src[i1];
#pragma unroll
    for (int k = 0; k < 2; k++) {
        const float4 v = k ? v1 : v0;
        const int i = k ? i1 : i0;
        __nv_bfloat16 hx = __float2bfloat16(v.x), hy = __float2bfloat16(v.y);
        __nv_bfloat16 hz = __float2bfloat16(v.z), hw = __float2bfloat16(v.w);
        uint2 h, l;
        h.x = (uint32_t)__bfloat16_as_ushort(hx) | ((uint32_t)__bfloat16_as_ushort(hy) << 16);
        h.y = (uint32_t)__bfloat16_as_ushort(hz) | ((uint32_t)__bfloat16_as_ushort(hw) << 16);
        l.x = bfpack(v.x - __bfloat162float(hx), v.y - __bfloat162float(hy));
        l.y = bfpack(v.z - __bfloat162float(hz), v.w - __bfloat162float(hw));
        hi[i] = h;
        lo[i] = l;
    }
}

// ---------------------------------------------------------------------------
// HMMA GEMM v3 (proven R8): CTA tile 128x256, 8 warps, warp tile 64x64.
// ---------------------------------------------------------------------------
__global__ __launch_bounds__(256, 1)
void gemm_mma_kernel(const __nv_bfloat16* __restrict__ Ah, const __nv_bfloat16* __restrict__ Al,
                     const __nv_bfloat16* __restrict__ Bh, const __nv_bfloat16* __restrict__ Bl,
                     const float* __restrict__ bias, float* __restrict__ C,
                     __nv_bfloat16* __restrict__ Vh, __nv_bfloat16* __restrict__ Vl, int N)
{
    extern __shared__ __align__(128) char smem[];
    const uint32_t sbase = smem_u32(smem);
    const int tid = threadIdx.x;
    const int lane = tid & 31, wid = tid >> 5;
    const int wm = wid >> 2, wn = wid & 3;
    const int bm = blockIdx.y << 7, bn = blockIdx.x << 8;

    auto load_stage = [&](int kc, int st_idx) {
        const uint32_t st = sbase + (uint32_t)st_idx * STG_B;
        const int koff = kc << 5;
#pragma unroll
        for (int i = 0; i < 4; i++) {
            const int idx = tid + (i << 8);
            const int mat = idx >> 9;
            const int row = (idx >> 2) & 127;
            const int c = idx & 3;
            const uint32_t so = (uint32_t)(mat * SA_B + row * ROW_B + c * 16);
            const __nv_bfloat16* src = (mat ? Al : Ah) + (size_t)(bm + row) * GK + koff + (c << 3);
            CP_ASYNC16(st + so, src);
        }
#pragma unroll
        for (int i = 0; i < 8; i++) {
            const int idx = tid + (i << 8);
            const int mat = idx >> 10;
            const int row = (idx >> 2) & 255;
            const int c = idx & 3;
            const uint32_t so = (uint32_t)(2 * SA_B + mat * SB_B + row * ROW_B + c * 16);
            const __nv_bfloat16* src = (mat ? Bl : Bh) + (size_t)(bn + row) * GK + koff + (c << 3);
            CP_ASYNC16(st + so, src);
        }
    };

    uint32_t aoff[4], boff[4];
#pragma unroll
    for (int mt = 0; mt < 4; mt++)
        aoff[mt] = (uint32_t)((wm * 64 + mt * 16 + (lane & 15)) * ROW_B + (lane >> 4) * 16);
#pragma unroll
    for (int gg = 0; gg < 4; gg++)
        boff[gg] = (uint32_t)((wn * 64 + gg * 16 + ((lane >> 4) & 1) * 8 + (lane & 7)) * ROW_B
                              + ((lane >> 3) & 1) * 16);

    float acc[4][8][4];
#pragma unroll
    for (int i = 0; i < 4; i++)
#pragma unroll
        for (int j = 0; j < 8; j++)
#pragma unroll
            for (int r = 0; r < 4; r++) acc[i][j][r] = 0.f;

    load_stage(0, 0); CP_COMMIT();
    load_stage(1, 1); CP_COMMIT();

    int s = 0;
    for (int kc = 0; kc < GKC; kc++) {
        CP_WAIT1();
        __syncthreads();
        if (kc + 2 < GKC) load_stage(kc + 2, (kc + 2) % 3);
        CP_COMMIT();

        const uint32_t st = sbase + (uint32_t)s * STG_B;
#pragma unroll
        for (int ks = 0; ks < 2; ks++) {
            const uint32_t ko = (uint32_t)(ks * 32);
            uint32_t ah[4][4], al[4][4];
#pragma unroll
            for (int mt = 0; mt < 4; mt++) {
                LDSM_X4(ah[mt], st + aoff[mt] + ko);
                LDSM_X4(al[mt], st + SA_B + aoff[mt] + ko);
            }
#pragma unroll
            for (int gg = 0; gg < 4; gg++) {
                uint32_t bh4[4], bl4[4];
                LDSM_X4(bh4, st + 2 * SA_B + boff[gg] + ko);
                LDSM_X4(bl4, st + 2 * SA_B + SB_B + boff[gg] + ko);
#pragma unroll
                for (int mt = 0; mt < 4; mt++) {
                    MMA_BF16(acc[mt][gg * 2],     ah[mt], bh4[0], bh4[1]);
                    MMA_BF16(acc[mt][gg * 2 + 1], ah[mt], bh4[2], bh4[3]);
                }
#pragma unroll
                for (int mt = 0; mt < 4; mt++) {
                    MMA_BF16(acc[mt][gg * 2],     ah[mt], bl4[0], bl4[1]);
                    MMA_BF16(acc[mt][gg * 2 + 1], ah[mt], bl4[2], bl4[3]);
                }
#pragma unroll
                for (int mt = 0; mt < 4; mt++) {
                    MMA_BF16(acc[mt][gg * 2],     al[mt], bh4[0], bh4[1]);
                    MMA_BF16(acc[mt][gg * 2 + 1], al[mt], bh4[2], bh4[3]);
                }
            }
        }
        s++; if (s == 3) s = 0;
    }

    const bool vsplit = (Vh != nullptr) && (bn >= 2048);
#pragma unroll
    for (int mt = 0; mt < 4; mt++) {
        const int r0 = bm + wm * 64 + mt * 16 + (lane >> 2);
#pragma unroll
        for (int j = 0; j < 8; j++) {
            const int colg = bn + wn * 64 + (j >> 1) * 16 + (j & 1) * 8 + (lane & 3) * 2;
            const float b0 = bias[colg], b1 = bias[colg + 1];
            const float v00 = acc[mt][j][0] + b0, v01 = acc[mt][j][1] + b1;
            const float v10 = acc[mt][j][2] + b0, v11 = acc[mt][j][3] + b1;
            if (!vsplit) {
                *(float2*)(C + (size_t)r0 * N + colg) = make_float2(v00, v01);
                *(float2*)(C + (size_t)(r0 + 8) * N + colg) = make_float2(v10, v11);
            } else {
                const int cv = colg - 2048;
                uint32_t* vh32 = (uint32_t*)Vh;
                uint32_t* vl32 = (uint32_t*)Vl;
                {
                    __nv_bfloat16 h0 = __float2bfloat16(v00), h1 = __float2bfloat16(v01);
                    uint32_t ph = (uint32_t)__bfloat16_as_ushort(h0) |
                                  ((uint32_t)__bfloat16_as_ushort(h1) << 16);
                    uint32_t pl = bfpack(v00 - __bfloat162float(h0), v01 - __bfloat162float(h1));
                    vh32[((size_t)r0 * 1024 + cv) >> 1] = ph;
                    vl32[((size_t)r0 * 1024 + cv) >> 1] = pl;
                }
                {
                    __nv_bfloat16 h0 = __float2bfloat16(v10), h1 = __float2bfloat16(v11);
                    uint32_t ph = (uint32_t)__bfloat16_as_ushort(h0) |
                                  ((uint32_t)__bfloat16_as_ushort(h1) << 16);
                    uint32_t pl = bfpack(v10 - __bfloat162float(h0), v11 - __bfloat162float(h1));
                    vh32[((size_t)(r0 + 8) * 1024 + cv) >> 1] = ph;
                    vl32[((size_t)(r0 + 8) * 1024 + cv) >> 1] = pl;
                }
            }
        }
    }
}

// ---------------------------------------------------------------------------
// conv -> GELU -> LN -> partial mean over a 128-t chunk. Grid (16, 32).
// ---------------------------------------------------------------------------
__global__ __launch_bounds__(256)
void conv_part_kernel(const float* __restrict__ conv_w, const float* __restrict__ conv_b,
                      const float* __restrict__ ln_g, const float* __restrict__ ln_b)
{
    const int chunk = blockIdx.x;
    const int nh = blockIdx.y;
    const int n = nh >> 4, h = nh & 15;
    const int tid = threadIdx.x;
    const int w = tid >> 5, lane = tid & 31;
    const int d0 = lane, d1 = lane + 32;
    const float* qbase = g_qkv + (size_t)n * L_SEQ * QKV_STRIDE + h * DH;

    const float cw00 = conv_w[d0 * 3 + 0], cw01 = conv_w[d0 * 3 + 1], cw02 = conv_w[d0 * 3 + 2];
    const float cw10 = conv_w[d1 * 3 + 0], cw11 = conv_w[d1 * 3 + 1], cw12 = conv_w[d1 * 3 + 2];
    const float cb0 = conv_b[d0], cb1 = conv_b[d1];
    const float lg0 = ln_g[d0], lb0 = ln_b[d0];
    const float lg1 = ln_g[d1], lb1 = ln_b[d1];

    float p0 = 0.f, p1 = 0.f;
#pragma unroll 4
    for (int i = 0; i < 16; i++) {
        const int t = chunk * 128 + (w << 4) + i;
        float c0 = cb0, c1 = cb1;
        {
            const float* r = qbase + (size_t)t * QKV_STRIDE;
            c0 = fmaf(r[d0], cw02, c0); c1 = fmaf(r[d1], cw12, c1);
        }
        if (t >= 1) {
            const float* r = qbase + (size_t)(t - 1) * QKV_STRIDE;
            c0 = fmaf(r[d0], cw01, c0); c1 = fmaf(r[d1], cw11, c1);
        }
        if (t >= 2) {
            const float* r = qbase + (size_t)(t - 2) * QKV_STRIDE;
            c0 = fmaf(r[d0], cw00, c0); c1 = fmaf(r[d1], cw10, c1);
        }
        float g0 = 0.5f * c0 * (1.f + erff(c0 * 0.70710678118654752f));
        float g1 = 0.5f * c1 * (1.f + erff(c1 * 0.70710678118654752f));
        float sv = g0 + g1, sq = g0 * g0 + g1 * g1;
#pragma unroll
        for (int o = 16; o; o >>= 1) {
            sv += __shfl_xor_sync(0xffffffffu, sv, o);
            sq += __shfl_xor_sync(0xffffffffu, sq, o);
        }
        float mu = sv * (1.f / 64.f);
        float var = sq * (1.f / 64.f) - mu * mu;
        float rs = rsqrtf(var + 1e-5f);
        p0 += (g0 - mu) * rs * lg0 + lb0;
        p1 += (g1 - mu) * rs * lg1 + lb1;
    }

    __shared__ float part[8][64];
    part[w][d0] = p0;
    part[w][d1] = p1;
    __syncthreads();
    if (tid < 64) {
        float sv = 0.f;
#pragma unroll
        for (int i = 0; i < 8; i++) sv += part[i][tid];
        g_cpart[(nh * 16 + chunk) * 64 + tid] = sv;
    }
}

// ---------------------------------------------------------------------------
// Reduce conv partials -> q_rel -> Wk -> L1 norm -> Wn bf16 split. (merged)
// ---------------------------------------------------------------------------
__global__ __launch_bounds__(256)
void wk_kernel()
{
    const int nh = blockIdx.x;
    const int n = nh >> 4, h = nh & 15;
    const int tid = threadIdx.x;
    __shared__ float4 qs4[16];
    if (tid < 64) {
        float sv = 0.f;
#pragma unroll
        for (int i = 0; i < 16; i++) sv += g_cpart[(nh * 16 + i) * 64 + tid];
        ((float*)qs4)[tid] = sv * (0.125f / 2048.f);
    }
    __syncthreads();

    const float* kbase = g_qkv + (size_t)n * L_SEQ * QKV_STRIDE + D_MODEL + h * DH;
    float wk[8];
    float la = 0.f;
#pragma unroll
    for (int i = 0; i < 8; i++) {
        int l = tid + i * 256;
        const float4* kr = (const float4*)(kbase + (size_t)l * QKV_STRIDE);
        float a = 0.f;
#pragma unroll
        for (int d4 = 0; d4 < 16; d4++) {
            float4 kv = kr[d4]; float4 q = qs4[d4];
            a = fmaf(q.x, kv.x, a); a = fmaf(q.y, kv.y, a);
            a = fmaf(q.z, kv.z, a); a = fmaf(q.w, kv.w, a);
        }
        wk[i] = a;
        la += fabsf(a);
    }
    __shared__ float red[256];
    red[tid] = la;
    __syncthreads();
    for (int o = 128; o; o >>= 1) {
        if (tid < o) red[tid] += red[tid + o];
        __syncthreads();
    }
    const float scale = 1.f / (red[0] + 1e-6f);
#pragma unroll
    for (int i = 0; i < 8; i++) {
        const float wv = wk[i] * scale;
        __nv_bfloat16 hh = __float2bfloat16(wv);
        g_wnh[nh * L_SEQ + tid + i * 256] = hh;
        g_wnl[nh * L_SEQ + tid + i * 256] = __float2bfloat16(wv - __bfloat162float(hh));
    }
}

// ---------------------------------------------------------------------------
// Toeplitz attention via HMMA v4 (R12 exact): 8 warps x 32 t-rows (2 m-tiles
// each), 256 t-rows per CTA, double-buffered cp.async, heavy-first,
// per-warp diagonal skip. launch_bounds(256,1) — NO reg cap (R13 spilled).
// ---------------------------------------------------------------------------
__global__ __launch_bounds__(256, 1)
void attn_mma_kernel()
{
    const int bid = blockIdx.x;
    const int g8 = 7 - (bid >> 5);
    const int nh = bid & 31;
    const int n = nh >> 4, h = nh & 15;
    const int tid = threadIdx.x;
    const int lane = tid & 31, w = tid >> 5;
    const int t_base = g8 << 8;
    const int C = 4 * g8 + 4;

    __shared__ __align__(16) char vsm[2][2][64 * VROW];
    __shared__ __nv_bfloat16 wseg[2][2][320];

    const uint32_t vbase = smem_u32(vsm);
    const __nv_bfloat16* wnh = g_wnh + nh * L_SEQ;
    const __nv_bfloat16* wnl = g_wnl + nh * L_SEQ;
    const __nv_bfloat16 zero = __float2bfloat16(0.f);

    auto load_w = [&](int c, int buf) {
        const int base = t_base - (c << 6) - 63;
        {
            const int j = tid;
            const int lag = base + j;
            wseg[buf][0][j] = (lag >= 0) ? wnh[lag] : zero;
            wseg[buf][1][j] = (lag >= 0) ? wnl[lag] : zero;
        }
        if (tid < 64) {
            const int j = 256 + tid;
            const int lag = base + j;
            wseg[buf][0][j] = (lag >= 0) ? wnh[lag] : zero;
            wseg[buf][1][j] = (lag >= 0) ? wnl[lag] : zero;
        }
    };
    auto load_v = [&](int c, int buf) {
        const uint32_t vb = vbase + (uint32_t)buf * (2 * 64 * VROW);
#pragma unroll
        for (int i = 0; i < 2; i++) {
            const int idx = tid + (i << 8);
            const int row = idx >> 3, ch = idx & 7;
            const size_t ga = (size_t)(n * L_SEQ + (c << 6) + row) * 1024 + h * DH + (ch << 3);
            const uint32_t so = (uint32_t)(row * VROW + (ch << 4));
            CP_ASYNC16(vb + so,             g_vh + ga);
            CP_ASYNC16(vb + so + 64 * VROW, g_vl + ga);
        }
    };

    float acc[2][8][4];
#pragma unroll
    for (int m = 0; m < 2; m++)
#pragma unroll
        for (int i = 0; i < 8; i++)
#pragma unroll
            for (int j = 0; j < 4; j++) acc[m][i][j] = 0.f;

    load_w(0, 0); load_v(0, 0); CP_COMMIT();

    const int r0 = lane >> 2;
    const int c0 = (lane & 3) << 1;
    const uint32_t lrow = (uint32_t)(lane & 15);
    const uint32_t lcol = (uint32_t)((lane >> 4) << 4);

    for (int c = 0; c < C; c++) {
        const int buf = c & 1;
        if (c + 1 < C) {
            load_w(c + 1, buf ^ 1);
            load_v(c + 1, buf ^ 1);
            CP_COMMIT();
            CP_WAIT1();
        } else {
            CP_WAIT0();
        }
        __syncthreads();

        if (t_base + (w << 5) + 31 >= (c << 6)) {
            const __nv_bfloat16* wh = wseg[buf][0];
            const __nv_bfloat16* wl = wseg[buf][1];
            const uint32_t vh_s = vbase + (uint32_t)buf * (2 * 64 * VROW);
            const uint32_t vl_s = vh_s + 64 * VROW;

#pragma unroll
            for (int ks = 0; ks < 4; ks++) {
                const int jbw = 63 + (w << 5) + r0 - (ks << 4) - c0;
                uint32_t hA = (uint32_t)__bfloat16_as_ushort(wh[jbw - 8]) |
                              ((uint32_t)__bfloat16_as_ushort(wh[jbw - 9]) << 16);
                uint32_t hB = (uint32_t)__bfloat16_as_ushort(wh[jbw]) |
                              ((uint32_t)__bfloat16_as_ushort(wh[jbw - 1]) << 16);
                uint32_t hCq = (uint32_t)__bfloat16_as_ushort(wh[jbw + 8]) |
                              ((uint32_t)__bfloat16_as_ushort(wh[jbw + 7]) << 16);
                uint32_t hD = (uint32_t)__bfloat16_as_ushort(wh[jbw + 16]) |
                              ((uint32_t)__bfloat16_as_ushort(wh[jbw + 15]) << 16);
                uint32_t hE = (uint32_t)__bfloat16_as_ushort(wh[jbw + 24]) |
                              ((uint32_t)__bfloat16_as_ushort(wh[jbw + 23]) << 16);
                uint32_t lA = (uint32_t)__bfloat16_as_ushort(wl[jbw - 8]) |
                              ((uint32_t)__bfloat16_as_ushort(wl[jbw - 9]) << 16);
                uint32_t lB = (uint32_t)__bfloat16_as_ushort(wl[jbw]) |
                              ((uint32_t)__bfloat16_as_ushort(wl[jbw - 1]) << 16);
                uint32_t lCq = (uint32_t)__bfloat16_as_ushort(wl[jbw + 8]) |
                              ((uint32_t)__bfloat16_as_ushort(wl[jbw + 7]) << 16);
                uint32_t lD = (uint32_t)__bfloat16_as_ushort(wl[jbw + 16]) |
                              ((uint32_t)__bfloat16_as_ushort(wl[jbw + 15]) << 16);
                uint32_t lE = (uint32_t)__bfloat16_as_ushort(wl[jbw + 24]) |
                              ((uint32_t)__bfloat16_as_ushort(wl[jbw + 23]) << 16);
                uint32_t a0h[4] = {hB, hCq, hA, hB};
                uint32_t a1h[4] = {hD, hE, hCq, hD};
                uint32_t a0l[4] = {lB, lCq, lA, lB};
                uint32_t a1l[4] = {lD, lE, lCq, lD};

                const uint32_t radd = (uint32_t)((ks * 16 + lrow) * VROW) + lcol;
#pragma unroll
                for (int gg = 0; gg < 4; gg++) {
                    uint32_t bh4[4], bl4[4];
                    const uint32_t ga = radd + (uint32_t)(gg << 5);
                    LDSM_X4_T(bh4, vh_s + ga);
                    LDSM_X4_T(bl4, vl_s + ga);
                    MMA_BF16(acc[0][gg * 2],     a0h, bh4[0], bh4[1]);
                    MMA_BF16(acc[0][gg * 2 + 1], a0h, bh4[2], bh4[3]);
                    MMA_BF16(acc[1][gg * 2],     a1h, bh4[0], bh4[1]);
                    MMA_BF16(acc[1][gg * 2 + 1], a1h, bh4[2], bh4[3]);
                    MMA_BF16(acc[0][gg * 2],     a0h, bl4[0], bl4[1]);
                    MMA_BF16(acc[0][gg * 2 + 1], a0h, bl4[2], bl4[3]);
                    MMA_BF16(acc[1][gg * 2],     a1l, bh4[0], bh4[1]);
                    MMA_BF16(acc[1][gg * 2 + 1], a1l, bh4[2], bh4[3]);
                    MMA_BF16(acc[0][gg * 2],     a0l, bh4[0], bh4[1]);
                    MMA_BF16(acc[0][gg * 2 + 1], a0l, bh4[2], bh4[3]);
                    MMA_BF16(acc[1][gg * 2],     a1h, bl4[0], bl4[1]);
                    MMA_BF16(acc[1][gg * 2 + 1], a1h, bl4[2], bl4[3]);
                }
            }
        }
        __syncthreads();
    }

    uint32_t* mh32 = (uint32_t*)g_ah;
    uint32_t* ml32 = (uint32_t*)g_al;
#pragma unroll
    for (int mt = 0; mt < 2; mt++) {
        const size_t rA = (size_t)(n * L_SEQ + t_base + (w << 5) + (mt << 4) + r0);
#pragma unroll
        for (int nb = 0; nb < 8; nb++) {
            const int col = h * DH + nb * 8 + c0;
            {
                float v0 = acc[mt][nb][0], v1 = acc[mt][nb][1];
                __nv_bfloat16 h0 = __float2bfloat16(v0), h1 = __float2bfloat16(v1);
                uint32_t ph = (uint32_t)__bfloat16_as_ushort(h0) |
                              ((uint32_t)__bfloat16_as_ushort(h1) << 16);
                uint32_t pl = bfpack(v0 - __bfloat162float(h0), v1 - __bfloat162float(h1));
                mh32[(rA * 1024 + col) >> 1] = ph;
                ml32[(rA * 1024 + col) >> 1] = pl;
            }
            {
                float v0 = acc[mt][nb][2], v1 = acc[mt][nb][3];
                __nv_bfloat16 h0 = __float2bfloat16(v0), h1 = __float2bfloat16(v1);
                uint32_t ph = (uint32_t)__bfloat16_as_ushort(h0) |
                              ((uint32_t)__bfloat16_as_ushort(h1) << 16);
                uint32_t pl = bfpack(v0 - __bfloat162float(h0), v1 - __bfloat162float(h1));
                mh32[((rA + 8) * 1024 + col) >> 1] = ph;
                ml32[((rA + 8) * 1024 + col) >> 1] = pl;
            }
        }
    }
}

__global__ void fill_kernel(float* p, int nfill, float v)
{
    int i = blockIdx.x * blockDim.x + threadIdx.x;
    if (i < nfill) p[i] = v;
}

// ---------------------------------------------------------------------------
extern "C" void kernel_launch(void* const* d_in, const int* in_sizes, int n_in,
                              void* d_out, int out_size)
{
    const float* x      = (const float*)d_in[0];
    const float* in_w   = (const float*)d_in[1];
    const float* in_b   = (const float*)d_in[2];
    const float* conv_w = (const float*)d_in[3];
    const float* conv_b = (const float*)d_in[4];
    const float* ln_g   = (const float*)d_in[5];
    const float* ln_b   = (const float*)d_in[6];
    const float* out_w  = (const float*)d_in[7];
    const float* out_b  = (const float*)d_in[8];
    float* out = (float*)d_out;

    void* p;
    cudaGetSymbolAddress(&p, g_qkv);    float* qkv = (float*)p;
    cudaGetSymbolAddress(&p, g_ah);     __nv_bfloat16* ah = (__nv_bfloat16*)p;
    cudaGetSymbolAddress(&p, g_al);     __nv_bfloat16* al = (__nv_bfloat16*)p;
    cudaGetSymbolAddress(&p, g_bh);     __nv_bfloat16* bh = (__nv_bfloat16*)p;
    cudaGetSymbolAddress(&p, g_bl);     __nv_bfloat16* bl = (__nv_bfloat16*)p;
    cudaGetSymbolAddress(&p, g_vh);     __nv_bfloat16* vh = (__nv_bfloat16*)p;
    cudaGetSymbolAddress(&p, g_vl);     __nv_bfloat16* vl = (__nv_bfloat16*)p;

    cudaFuncSetAttribute(gemm_mma_kernel, cudaFuncAttributeMaxDynamicSharedMemorySize, GT_SMEM);

    // splits for GEMM1 (2 float4 per thread)
    split_bf16_kernel<<<2048, 256>>>((const float4*)x, (uint2*)ah, (uint2*)al, 4096 * 1024 / 4);
    split_bf16_kernel<<<1536, 256>>>((const float4*)in_w, (uint2*)bh, (uint2*)bl, 3072 * 1024 / 4);

    // GEMM1 (merged): q,k cols -> qkv fp32; V cols -> bf16 hi/lo split (fused)
    gemm_mma_kernel<<<dim3(12, 32), 256, GT_SMEM>>>(ah, al, bh, bl, in_b, qkv, vh, vl, QKV_STRIDE);

    // conv -> gelu -> LN -> partial mean
    conv_part_kernel<<<dim3(16, NH_TOT), 256>>>(conv_w, conv_b, ln_g, ln_b);

    // reduce + Wk -> Wn (bf16 split), merged
    wk_kernel<<<NH_TOT, 256>>>();

    // causal Toeplitz attention (HMMA, R12 exact)
    attn_mma_kernel<<<256, 256>>>();

    // GEMM2: out = merged @ out_w^T + out_b
    split_bf16_kernel<<<512, 256>>>((const float4*)out_w, (uint2*)bh, (uint2*)bl, 1024 * 1024 / 4);
    gemm_mma_kernel<<<dim3(4, 32), 256, GT_SMEM>>>(ah, al, bh, bl, out_b, out,
                                                   nullptr, nullptr, D_MODEL);

    // mock attention weights
    int nmock = out_size - OUT_ELEMS;
    if (nmock > 0)
        fill_kernel<<<(nmock + 255) / 256, 256>>>(out + OUT_ELEMS, nmock, 1.0f / (float)L_SEQ);
}

// round 15
// speedup vs baseline: 1.0653x; 1.0055x over previous
#include <cuda_runtime.h>
#include <cuda_bf16.h>
#include <math.h>
#include <stdint.h>

// Problem constants
#define NBATCH 2
#define L_SEQ 2048
#define D_MODEL 1024
#define H_HEADS 16
#define DH 64
#define QKV_STRIDE 3072
#define NH_TOT (NBATCH * H_HEADS)
#define OUT_ELEMS (NBATCH * L_SEQ * D_MODEL)
#define GK 1024
#define GKC 32
// gemm smem: 3 stages x (A 128 rows + B 256 rows) x 2 mats x 80B
#define ROW_B 80
#define SA_B (128 * ROW_B)
#define SB_B (256 * ROW_B)
#define STG_B (2 * SA_B + 2 * SB_B)
#define GT_SMEM (3 * STG_B)

#define VROW 144

// Static device scratch
__device__ float g_qkv[(size_t)NBATCH * L_SEQ * QKV_STRIDE];
__device__ float g_cpart[NH_TOT * 16 * DH];
__device__ __align__(16) __nv_bfloat16 g_ah[(size_t)4096 * 1024];
__device__ __align__(16) __nv_bfloat16 g_al[(size_t)4096 * 1024];
__device__ __align__(16) __nv_bfloat16 g_bh[(size_t)3072 * 1024];
__device__ __align__(16) __nv_bfloat16 g_bl[(size_t)3072 * 1024];
__device__ __align__(16) __nv_bfloat16 g_owh[(size_t)1024 * 1024];  // out_w split
__device__ __align__(16) __nv_bfloat16 g_owl[(size_t)1024 * 1024];
__device__ __align__(16) __nv_bfloat16 g_vh[(size_t)4096 * 1024];
__device__ __align__(16) __nv_bfloat16 g_vl[(size_t)4096 * 1024];
__device__ __align__(16) __nv_bfloat16 g_wnh[NH_TOT * L_SEQ];
__device__ __align__(16) __nv_bfloat16 g_wnl[NH_TOT * L_SEQ];

// ---------------------------------------------------------------------------
__device__ __forceinline__ uint32_t smem_u32(const void* p) {
    uint32_t a;
    asm("{ .reg .u64 t; cvta.to.shared.u64 t, %1; cvt.u32.u64 %0, t; }" : "=r"(a) : "l"(p));
    return a;
}

#define CP_ASYNC16(dst, src) \
    asm volatile("cp.async.cg.shared.global [%0], [%1], 16;" :: "r"(dst), "l"(src))
#define CP_COMMIT() asm volatile("cp.async.commit_group;" ::: "memory")
#define CP_WAIT1()  asm volatile("cp.async.wait_group 1;" ::: "memory")
#define CP_WAIT0()  asm volatile("cp.async.wait_group 0;" ::: "memory")

#define LDSM_X4(r, addr) \
    asm volatile("ldmatrix.sync.aligned.m8n8.x4.shared.b16 {%0,%1,%2,%3}, [%4];" \
        : "=r"((r)[0]), "=r"((r)[1]), "=r"((r)[2]), "=r"((r)[3]) : "r"(addr))

#define LDSM_X4_T(r, addr) \
    asm volatile("ldmatrix.sync.aligned.m8n8.x4.trans.shared.b16 {%0,%1,%2,%3}, [%4];" \
        : "=r"((r)[0]), "=r"((r)[1]), "=r"((r)[2]), "=r"((r)[3]) : "r"(addr))

#define MMA_BF16(d, a, b0, b1) \
    asm volatile("mma.sync.aligned.m16n8k16.row.col.f32.bf16.bf16.f32 " \
        "{%0,%1,%2,%3}, {%4,%5,%6,%7}, {%8,%9}, {%0,%1,%2,%3};" \
        : "+f"((d)[0]), "+f"((d)[1]), "+f"((d)[2]), "+f"((d)[3]) \
        : "r"((a)[0]), "r"((a)[1]), "r"((a)[2]), "r"((a)[3]), "r"(b0), "r"(b1))

__device__ __forceinline__ uint32_t bfpack(float a, float b) {
    __nv_bfloat16 ha = __float2bfloat16(a), hb = __float2bfloat16(b);
    return (uint32_t)__bfloat16_as_ushort(ha) | ((uint32_t)__bfloat16_as_ushort(hb) << 16);
}

__device__ __forceinline__ void split_pair(const float4* __restrict__ src,
                                           uint2* __restrict__ hi, uint2* __restrict__ lo,
                                           int i0, int i1)
{
    float4 v0 = src[i0];
    float4 v1 = src[i1];
#pragma unroll
    for (int k = 0; k < 2; k++) {
        const float4 v = k ? v1 : v0;
        const int i = k ? i1 : i0;
        __nv_bfloat16 hx = __float2bfloat16(v.x), hy = __float2bfloat16(v.y);
        __nv_bfloat16 hz = __float2bfloat16(v.z), hw = __float2bfloat16(v.w);
        uint2 h, l;
        h.x = (uint32_t)__bfloat16_as_ushort(hx) | ((uint32_t)__bfloat16_as_ushort(hy) << 16);
        h.y = (uint32_t)__bfloat16_as_ushort(hz) | ((uint32_t)__bfloat16_as_ushort(hw) << 16);
        l.x = bfpack(v.x - __bfloat162float(hx), v.y - __bfloat162float(hy));
        l.y = bfpack(v.z - __bfloat162float(hz), v.w - __bfloat162float(hw));
        hi[i] = h;
        lo[i] = l;
    }
}

// ---------------------------------------------------------------------------
// One launch splitting x, in_proj_w and out_w (all independent of upstream).
// Blocks [0,2048): x -> ah/al; [2048,3584): in_w -> bh/bl; [3584,4096): out_w
// -> owh/owl. 2 independent float4 per thread (MLP=2).
// ---------------------------------------------------------------------------
__global__ __launch_bounds__(256)
void split_all_kernel(const float4* __restrict__ x, const float4* __restrict__ in_w,
                      const float4* __restrict__ out_w)
{
    const int b = blockIdx.x;
    const int t = threadIdx.x;
    if (b < 2048) {
        const int i0 = b * 256 + t;               // half = 2048*256
        split_pair(x, (uint2*)g_ah, (uint2*)g_al, i0, i0 + 2048 * 256);
    } else if (b < 3584) {
        const int i0 = (b - 2048) * 256 + t;      // half = 1536*256
        split_pair(in_w, (uint2*)g_bh, (uint2*)g_bl, i0, i0 + 1536 * 256);
    } else {
        const int i0 = (b - 3584) * 256 + t;      // half = 512*256
        split_pair(out_w, (uint2*)g_owh, (uint2*)g_owl, i0, i0 + 512 * 256);
    }
}

// ---------------------------------------------------------------------------
// HMMA GEMM v3 (proven R8): CTA tile 128x256, 8 warps, warp tile 64x64.
// ---------------------------------------------------------------------------
__global__ __launch_bounds__(256, 1)
void gemm_mma_kernel(const __nv_bfloat16* __restrict__ Ah, const __nv_bfloat16* __restrict__ Al,
                     const __nv_bfloat16* __restrict__ Bh, const __nv_bfloat16* __restrict__ Bl,
                     const float* __restrict__ bias, float* __restrict__ C,
                     __nv_bfloat16* __restrict__ Vh, __nv_bfloat16* __restrict__ Vl, int N)
{
    extern __shared__ __align__(128) char smem[];
    const uint32_t sbase = smem_u32(smem);
    const int tid = threadIdx.x;
    const int lane = tid & 31, wid = tid >> 5;
    const int wm = wid >> 2, wn = wid & 3;
    const int bm = blockIdx.y << 7, bn = blockIdx.x << 8;

    auto load_stage = [&](int kc, int st_idx) {
        const uint32_t st = sbase + (uint32_t)st_idx * STG_B;
        const int koff = kc << 5;
#pragma unroll
        for (int i = 0; i < 4; i++) {
            const int idx = tid + (i << 8);
            const int mat = idx >> 9;
            const int row = (idx >> 2) & 127;
            const int c = idx & 3;
            const uint32_t so = (uint32_t)(mat * SA_B + row * ROW_B + c * 16);
            const __nv_bfloat16* src = (mat ? Al : Ah) + (size_t)(bm + row) * GK + koff + (c << 3);
            CP_ASYNC16(st + so, src);
        }
#pragma unroll
        for (int i = 0; i < 8; i++) {
            const int idx = tid + (i << 8);
            const int mat = idx >> 10;
            const int row = (idx >> 2) & 255;
            const int c = idx & 3;
            const uint32_t so = (uint32_t)(2 * SA_B + mat * SB_B + row * ROW_B + c * 16);
            const __nv_bfloat16* src = (mat ? Bl : Bh) + (size_t)(bn + row) * GK + koff + (c << 3);
            CP_ASYNC16(st + so, src);
        }
    };

    uint32_t aoff[4], boff[4];
#pragma unroll
    for (int mt = 0; mt < 4; mt++)
        aoff[mt] = (uint32_t)((wm * 64 + mt * 16 + (lane & 15)) * ROW_B + (lane >> 4) * 16);
#pragma unroll
    for (int gg = 0; gg < 4; gg++)
        boff[gg] = (uint32_t)((wn * 64 + gg * 16 + ((lane >> 4) & 1) * 8 + (lane & 7)) * ROW_B
                              + ((lane >> 3) & 1) * 16);

    float acc[4][8][4];
#pragma unroll
    for (int i = 0; i < 4; i++)
#pragma unroll
        for (int j = 0; j < 8; j++)
#pragma unroll
            for (int r = 0; r < 4; r++) acc[i][j][r] = 0.f;

    load_stage(0, 0); CP_COMMIT();
    load_stage(1, 1); CP_COMMIT();

    int s = 0;
    for (int kc = 0; kc < GKC; kc++) {
        CP_WAIT1();
        __syncthreads();
        if (kc + 2 < GKC) load_stage(kc + 2, (kc + 2) % 3);
        CP_COMMIT();

        const uint32_t st = sbase + (uint32_t)s * STG_B;
#pragma unroll
        for (int ks = 0; ks < 2; ks++) {
            const uint32_t ko = (uint32_t)(ks * 32);
            uint32_t ah[4][4], al[4][4];
#pragma unroll
            for (int mt = 0; mt < 4; mt++) {
                LDSM_X4(ah[mt], st + aoff[mt] + ko);
                LDSM_X4(al[mt], st + SA_B + aoff[mt] + ko);
            }
#pragma unroll
            for (int gg = 0; gg < 4; gg++) {
                uint32_t bh4[4], bl4[4];
                LDSM_X4(bh4, st + 2 * SA_B + boff[gg] + ko);
                LDSM_X4(bl4, st + 2 * SA_B + SB_B + boff[gg] + ko);
#pragma unroll
                for (int mt = 0; mt < 4; mt++) {
                    MMA_BF16(acc[mt][gg * 2],     ah[mt], bh4[0], bh4[1]);
                    MMA_BF16(acc[mt][gg * 2 + 1], ah[mt], bh4[2], bh4[3]);
                }
#pragma unroll
                for (int mt = 0; mt < 4; mt++) {
                    MMA_BF16(acc[mt][gg * 2],     ah[mt], bl4[0], bl4[1]);
                    MMA_BF16(acc[mt][gg * 2 + 1], ah[mt], bl4[2], bl4[3]);
                }
#pragma unroll
                for (int mt = 0; mt < 4; mt++) {
                    MMA_BF16(acc[mt][gg * 2],     al[mt], bh4[0], bh4[1]);
                    MMA_BF16(acc[mt][gg * 2 + 1], al[mt], bh4[2], bh4[3]);
                }
            }
        }
        s++; if (s == 3) s = 0;
    }

    const bool vsplit = (Vh != nullptr) && (bn >= 2048);
#pragma unroll
    for (int mt = 0; mt < 4; mt++) {
        const int r0 = bm + wm * 64 + mt * 16 + (lane >> 2);
#pragma unroll
        for (int j = 0; j < 8; j++) {
            const int colg = bn + wn * 64 + (j >> 1) * 16 + (j & 1) * 8 + (lane & 3) * 2;
            const float b0 = bias[colg], b1 = bias[colg + 1];
            const float v00 = acc[mt][j][0] + b0, v01 = acc[mt][j][1] + b1;
            const float v10 = acc[mt][j][2] + b0, v11 = acc[mt][j][3] + b1;
            if (!vsplit) {
                *(float2*)(C + (size_t)r0 * N + colg) = make_float2(v00, v01);
                *(float2*)(C + (size_t)(r0 + 8) * N + colg) = make_float2(v10, v11);
            } else {
                const int cv = colg - 2048;
                uint32_t* vh32 = (uint32_t*)Vh;
                uint32_t* vl32 = (uint32_t*)Vl;
                {
                    __nv_bfloat16 h0 = __float2bfloat16(v00), h1 = __float2bfloat16(v01);
                    uint32_t ph = (uint32_t)__bfloat16_as_ushort(h0) |
                                  ((uint32_t)__bfloat16_as_ushort(h1) << 16);
                    uint32_t pl = bfpack(v00 - __bfloat162float(h0), v01 - __bfloat162float(h1));
                    vh32[((size_t)r0 * 1024 + cv) >> 1] = ph;
                    vl32[((size_t)r0 * 1024 + cv) >> 1] = pl;
                }
                {
                    __nv_bfloat16 h0 = __float2bfloat16(v10), h1 = __float2bfloat16(v11);
                    uint32_t ph = (uint32_t)__bfloat16_as_ushort(h0) |
                                  ((uint32_t)__bfloat16_as_ushort(h1) << 16);
                    uint32_t pl = bfpack(v10 - __bfloat162float(h0), v11 - __bfloat162float(h1));
                    vh32[((size_t)(r0 + 8) * 1024 + cv) >> 1] = ph;
                    vl32[((size_t)(r0 + 8) * 1024 + cv) >> 1] = pl;
                }
            }
        }
    }
}

// ---------------------------------------------------------------------------
// conv -> GELU -> LN -> partial mean over a 128-t chunk. Grid (16, 32).
// ---------------------------------------------------------------------------
__global__ __launch_bounds__(256)
void conv_part_kernel(const float* __restrict__ conv_w, const float* __restrict__ conv_b,
                      const float* __restrict__ ln_g, const float* __restrict__ ln_b)
{
    const int chunk = blockIdx.x;
    const int nh = blockIdx.y;
    const int n = nh >> 4, h = nh & 15;
    const int tid = threadIdx.x;
    const int w = tid >> 5, lane = tid & 31;
    const int d0 = lane, d1 = lane + 32;
    const float* qbase = g_qkv + (size_t)n * L_SEQ * QKV_STRIDE + h * DH;

    const float cw00 = conv_w[d0 * 3 + 0], cw01 = conv_w[d0 * 3 + 1], cw02 = conv_w[d0 * 3 + 2];
    const float cw10 = conv_w[d1 * 3 + 0], cw11 = conv_w[d1 * 3 + 1], cw12 = conv_w[d1 * 3 + 2];
    const float cb0 = conv_b[d0], cb1 = conv_b[d1];
    const float lg0 = ln_g[d0], lb0 = ln_b[d0];
    const float lg1 = ln_g[d1], lb1 = ln_b[d1];

    float p0 = 0.f, p1 = 0.f;
#pragma unroll 4
    for (int i = 0; i < 16; i++) {
        const int t = chunk * 128 + (w << 4) + i;
        float c0 = cb0, c1 = cb1;
        {
            const float* r = qbase + (size_t)t * QKV_STRIDE;
            c0 = fmaf(r[d0], cw02, c0); c1 = fmaf(r[d1], cw12, c1);
        }
        if (t >= 1) {
            const float* r = qbase + (size_t)(t - 1) * QKV_STRIDE;
            c0 = fmaf(r[d0], cw01, c0); c1 = fmaf(r[d1], cw11, c1);
        }
        if (t >= 2) {
            const float* r = qbase + (size_t)(t - 2) * QKV_STRIDE;
            c0 = fmaf(r[d0], cw00, c0); c1 = fmaf(r[d1], cw10, c1);
        }
        float g0 = 0.5f * c0 * (1.f + erff(c0 * 0.70710678118654752f));
        float g1 = 0.5f * c1 * (1.f + erff(c1 * 0.70710678118654752f));
        float sv = g0 + g1, sq = g0 * g0 + g1 * g1;
#pragma unroll
        for (int o = 16; o; o >>= 1) {
            sv += __shfl_xor_sync(0xffffffffu, sv, o);
            sq += __shfl_xor_sync(0xffffffffu, sq, o);
        }
        float mu = sv * (1.f / 64.f);
        float var = sq * (1.f / 64.f) - mu * mu;
        float rs = rsqrtf(var + 1e-5f);
        p0 += (g0 - mu) * rs * lg0 + lb0;
        p1 += (g1 - mu) * rs * lg1 + lb1;
    }

    __shared__ float part[8][64];
    part[w][d0] = p0;
    part[w][d1] = p1;
    __syncthreads();
    if (tid < 64) {
        float sv = 0.f;
#pragma unroll
        for (int i = 0; i < 8; i++) sv += part[i][tid];
        g_cpart[(nh * 16 + chunk) * 64 + tid] = sv;
    }
}

// ---------------------------------------------------------------------------
// Reduce conv partials -> q_rel -> Wk -> L1 norm -> Wn bf16 split. (merged)
// ---------------------------------------------------------------------------
__global__ __launch_bounds__(256)
void wk_kernel()
{
    const int nh = blockIdx.x;
    const int n = nh >> 4, h = nh & 15;
    const int tid = threadIdx.x;
    __shared__ float4 qs4[16];
    if (tid < 64) {
        float sv = 0.f;
#pragma unroll
        for (int i = 0; i < 16; i++) sv += g_cpart[(nh * 16 + i) * 64 + tid];
        ((float*)qs4)[tid] = sv * (0.125f / 2048.f);
    }
    __syncthreads();

    const float* kbase = g_qkv + (size_t)n * L_SEQ * QKV_STRIDE + D_MODEL + h * DH;
    float wk[8];
    float la = 0.f;
#pragma unroll
    for (int i = 0; i < 8; i++) {
        int l = tid + i * 256;
        const float4* kr = (const float4*)(kbase + (size_t)l * QKV_STRIDE);
        float a = 0.f;
#pragma unroll
        for (int d4 = 0; d4 < 16; d4++) {
            float4 kv = kr[d4]; float4 q = qs4[d4];
            a = fmaf(q.x, kv.x, a); a = fmaf(q.y, kv.y, a);
            a = fmaf(q.z, kv.z, a); a = fmaf(q.w, kv.w, a);
        }
        wk[i] = a;
        la += fabsf(a);
    }
    __shared__ float red[256];
    red[tid] = la;
    __syncthreads();
    for (int o = 128; o; o >>= 1) {
        if (tid < o) red[tid] += red[tid + o];
        __syncthreads();
    }
    const float scale = 1.f / (red[0] + 1e-6f);
#pragma unroll
    for (int i = 0; i < 8; i++) {
        const float wv = wk[i] * scale;
        __nv_bfloat16 hh = __float2bfloat16(wv);
        g_wnh[nh * L_SEQ + tid + i * 256] = hh;
        g_wnl[nh * L_SEQ + tid + i * 256] = __float2bfloat16(wv - __bfloat162float(hh));
    }
}

// ---------------------------------------------------------------------------
// Toeplitz attention via HMMA v4 (R12/R14 exact): 8 warps x 32 t-rows
// (2 m-tiles each), 256 t-rows per CTA, double-buffered cp.async,
// heavy-first, per-warp diagonal skip.
// ---------------------------------------------------------------------------
__global__ __launch_bounds__(256, 1)
void attn_mma_kernel()
{
    const int bid = blockIdx.x;
    const int g8 = 7 - (bid >> 5);
    const int nh = bid & 31;
    const int n = nh >> 4, h = nh & 15;
    const int tid = threadIdx.x;
    const int lane = tid & 31, w = tid >> 5;
    const int t_base = g8 << 8;
    const int C = 4 * g8 + 4;

    __shared__ __align__(16) char vsm[2][2][64 * VROW];
    __shared__ __nv_bfloat16 wseg[2][2][320];

    const uint32_t vbase = smem_u32(vsm);
    const __nv_bfloat16* wnh = g_wnh + nh * L_SEQ;
    const __nv_bfloat16* wnl = g_wnl + nh * L_SEQ;
    const __nv_bfloat16 zero = __float2bfloat16(0.f);

    auto load_w = [&](int c, int buf) {
        const int base = t_base - (c << 6) - 63;
        {
            const int j = tid;
            const int lag = base + j;
            wseg[buf][0][j] = (lag >= 0) ? wnh[lag] : zero;
            wseg[buf][1][j] = (lag >= 0) ? wnl[lag] : zero;
        }
        if (tid < 64) {
            const int j = 256 + tid;
            const int lag = base + j;
            wseg[buf][0][j] = (lag >= 0) ? wnh[lag] : zero;
            wseg[buf][1][j] = (lag >= 0) ? wnl[lag] : zero;
        }
    };
    auto load_v = [&](int c, int buf) {
        const uint32_t vb = vbase + (uint32_t)buf * (2 * 64 * VROW);
#pragma unroll
        for (int i = 0; i < 2; i++) {
            const int idx = tid + (i << 8);
            const int row = idx >> 3, ch = idx & 7;
            const size_t ga = (size_t)(n * L_SEQ + (c << 6) + row) * 1024 + h * DH + (ch << 3);
            const uint32_t so = (uint32_t)(row * VROW + (ch << 4));
            CP_ASYNC16(vb + so,             g_vh + ga);
            CP_ASYNC16(vb + so + 64 * VROW, g_vl + ga);
        }
    };

    float acc[2][8][4];
#pragma unroll
    for (int m = 0; m < 2; m++)
#pragma unroll
        for (int i = 0; i < 8; i++)
#pragma unroll
            for (int j = 0; j < 4; j++) acc[m][i][j] = 0.f;

    load_w(0, 0); load_v(0, 0); CP_COMMIT();

    const int r0 = lane >> 2;
    const int c0 = (lane & 3) << 1;
    const uint32_t lrow = (uint32_t)(lane & 15);
    const uint32_t lcol = (uint32_t)((lane >> 4) << 4);

    for (int c = 0; c < C; c++) {
        const int buf = c & 1;
        if (c + 1 < C) {
            load_w(c + 1, buf ^ 1);
            load_v(c + 1, buf ^ 1);
            CP_COMMIT();
            CP_WAIT1();
        } else {
            CP_WAIT0();
        }
        __syncthreads();

        if (t_base + (w << 5) + 31 >= (c << 6)) {
            const __nv_bfloat16* wh = wseg[buf][0];
            const __nv_bfloat16* wl = wseg[buf][1];
            const uint32_t vh_s = vbase + (uint32_t)buf * (2 * 64 * VROW);
            const uint32_t vl_s = vh_s + 64 * VROW;

#pragma unroll
            for (int ks = 0; ks < 4; ks++) {
                const int jbw = 63 + (w << 5) + r0 - (ks << 4) - c0;
                uint32_t hA = (uint32_t)__bfloat16_as_ushort(wh[jbw - 8]) |
                              ((uint32_t)__bfloat16_as_ushort(wh[jbw - 9]) << 16);
                uint32_t hB = (uint32_t)__bfloat16_as_ushort(wh[jbw]) |
                              ((uint32_t)__bfloat16_as_ushort(wh[jbw - 1]) << 16);
                uint32_t hCq = (uint32_t)__bfloat16_as_ushort(wh[jbw + 8]) |
                              ((uint32_t)__bfloat16_as_ushort(wh[jbw + 7]) << 16);
                uint32_t hD = (uint32_t)__bfloat16_as_ushort(wh[jbw + 16]) |
                              ((uint32_t)__bfloat16_as_ushort(wh[jbw + 15]) << 16);
                uint32_t hE = (uint32_t)__bfloat16_as_ushort(wh[jbw + 24]) |
                              ((uint32_t)__bfloat16_as_ushort(wh[jbw + 23]) << 16);
                uint32_t lA = (uint32_t)__bfloat16_as_ushort(wl[jbw - 8]) |
                              ((uint32_t)__bfloat16_as_ushort(wl[jbw - 9]) << 16);
                uint32_t lB = (uint32_t)__bfloat16_as_ushort(wl[jbw]) |
                              ((uint32_t)__bfloat16_as_ushort(wl[jbw - 1]) << 16);
                uint32_t lCq = (uint32_t)__bfloat16_as_ushort(wl[jbw + 8]) |
                              ((uint32_t)__bfloat16_as_ushort(wl[jbw + 7]) << 16);
                uint32_t lD = (uint32_t)__bfloat16_as_ushort(wl[jbw + 16]) |
                              ((uint32_t)__bfloat16_as_ushort(wl[jbw + 15]) << 16);
                uint32_t lE = (uint32_t)__bfloat16_as_ushort(wl[jbw + 24]) |
                              ((uint32_t)__bfloat16_as_ushort(wl[jbw + 23]) << 16);
                uint32_t a0h[4] = {hB, hCq, hA, hB};
                uint32_t a1h[4] = {hD, hE, hCq, hD};
                uint32_t a0l[4] = {lB, lCq, lA, lB};
                uint32_t a1l[4] = {lD, lE, lCq, lD};

                const uint32_t radd = (uint32_t)((ks * 16 + lrow) * VROW) + lcol;
#pragma unroll
                for (int gg = 0; gg < 4; gg++) {
                    uint32_t bh4[4], bl4[4];
                    const uint32_t ga = radd + (uint32_t)(gg << 5);
                    LDSM_X4_T(bh4, vh_s + ga);
                    LDSM_X4_T(bl4, vl_s + ga);
                    MMA_BF16(acc[0][gg * 2],     a0h, bh4[0], bh4[1]);
                    MMA_BF16(acc[0][gg * 2 + 1], a0h, bh4[2], bh4[3]);
                    MMA_BF16(acc[1][gg * 2],     a1h, bh4[0], bh4[1]);
                    MMA_BF16(acc[1][gg * 2 + 1], a1h, bh4[2], bh4[3]);
                    MMA_BF16(acc[0][gg * 2],     a0h, bl4[0], bl4[1]);
                    MMA_BF16(acc[0][gg * 2 + 1], a0h, bl4[2], bl4[3]);
                    MMA_BF16(acc[1][gg * 2],     a1l, bh4[0], bh4[1]);
                    MMA_BF16(acc[1][gg * 2 + 1], a1l, bh4[2], bh4[3]);
                    MMA_BF16(acc[0][gg * 2],     a0l, bh4[0], bh4[1]);
                    MMA_BF16(acc[0][gg * 2 + 1], a0l, bh4[2], bh4[3]);
                    MMA_BF16(acc[1][gg * 2],     a1h, bl4[0], bl4[1]);
                    MMA_BF16(acc[1][gg * 2 + 1], a1h, bl4[2], bl4[3]);
                }
            }
        }
        __syncthreads();
    }

    uint32_t* mh32 = (uint32_t*)g_ah;
    uint32_t* ml32 = (uint32_t*)g_al;
#pragma unroll
    for (int mt = 0; mt < 2; mt++) {
        const size_t rA = (size_t)(n * L_SEQ + t_base + (w << 5) + (mt << 4) + r0);
#pragma unroll
        for (int nb = 0; nb < 8; nb++) {
            const int col = h * DH + nb * 8 + c0;
            {
                float v0 = acc[mt][nb][0], v1 = acc[mt][nb][1];
                __nv_bfloat16 h0 = __float2bfloat16(v0), h1 = __float2bfloat16(v1);
                uint32_t ph = (uint32_t)__bfloat16_as_ushort(h0) |
                              ((uint32_t)__bfloat16_as_ushort(h1) << 16);
                uint32_t pl = bfpack(v0 - __bfloat162float(h0), v1 - __bfloat162float(h1));
                mh32[(rA * 1024 + col) >> 1] = ph;
                ml32[(rA * 1024 + col) >> 1] = pl;
            }
            {
                float v0 = acc[mt][nb][2], v1 = acc[mt][nb][3];
                __nv_bfloat16 h0 = __float2bfloat16(v0), h1 = __float2bfloat16(v1);
                uint32_t ph = (uint32_t)__bfloat16_as_ushort(h0) |
                              ((uint32_t)__bfloat16_as_ushort(h1) << 16);
                uint32_t pl = bfpack(v0 - __bfloat162float(h0), v1 - __bfloat162float(h1));
                mh32[((rA + 8) * 1024 + col) >> 1] = ph;
                ml32[((rA + 8) * 1024 + col) >> 1] = pl;
            }
        }
    }
}

__global__ void fill_kernel(float* p, int nfill, float v)
{
    int i = blockIdx.x * blockDim.x + threadIdx.x;
    if (i < nfill) p[i] = v;
}

// ---------------------------------------------------------------------------
extern "C" void kernel_launch(void* const* d_in, const int* in_sizes, int n_in,
                              void* d_out, int out_size)
{
    const float* x      = (const float*)d_in[0];
    const float* in_w   = (const float*)d_in[1];
    const float* in_b   = (const float*)d_in[2];
    const float* conv_w = (const float*)d_in[3];
    const float* conv_b = (const float*)d_in[4];
    const float* ln_g   = (const float*)d_in[5];
    const float* ln_b   = (const float*)d_in[6];
    const float* out_w  = (const float*)d_in[7];
    const float* out_b  = (const float*)d_in[8];
    float* out = (float*)d_out;

    void* p;
    cudaGetSymbolAddress(&p, g_qkv);    float* qkv = (float*)p;
    cudaGetSymbolAddress(&p, g_ah);     __nv_bfloat16* ah = (__nv_bfloat16*)p;
    cudaGetSymbolAddress(&p, g_al);     __nv_bfloat16* al = (__nv_bfloat16*)p;
    cudaGetSymbolAddress(&p, g_bh);     __nv_bfloat16* bh = (__nv_bfloat16*)p;
    cudaGetSymbolAddress(&p, g_bl);     __nv_bfloat16* bl = (__nv_bfloat16*)p;
    cudaGetSymbolAddress(&p, g_owh);    __nv_bfloat16* owh = (__nv_bfloat16*)p;
    cudaGetSymbolAddress(&p, g_owl);    __nv_bfloat16* owl = (__nv_bfloat16*)p;
    cudaGetSymbolAddress(&p, g_vh);     __nv_bfloat16* vh = (__nv_bfloat16*)p;
    cudaGetSymbolAddress(&p, g_vl);     __nv_bfloat16* vl = (__nv_bfloat16*)p;

    cudaFuncSetAttribute(gemm_mma_kernel, cudaFuncAttributeMaxDynamicSharedMemorySize, GT_SMEM);

    // mock attention weights (independent — run first)
    int nmock = out_size - OUT_ELEMS;
    if (nmock > 0)
        fill_kernel<<<(nmock + 255) / 256, 256>>>(out + OUT_ELEMS, nmock, 1.0f / (float)L_SEQ);

    // all input splits in one launch: x, in_w, out_w
    split_all_kernel<<<4096, 256>>>((const float4*)x, (const float4*)in_w, (const float4*)out_w);

    // GEMM1 (merged): q,k cols -> qkv fp32; V cols -> bf16 hi/lo split (fused)
    gemm_mma_kernel<<<dim3(12, 32), 256, GT_SMEM>>>(ah, al, bh, bl, in_b, qkv, vh, vl, QKV_STRIDE);

    // conv -> gelu -> LN -> partial mean
    conv_part_kernel<<<dim3(16, NH_TOT), 256>>>(conv_w, conv_b, ln_g, ln_b);

    // reduce + Wk -> Wn (bf16 split), merged
    wk_kernel<<<NH_TOT, 256>>>();

    // causal Toeplitz attention (HMMA) -> merged split in g_ah/g_al
    attn_mma_kernel<<<256, 256>>>();

    // GEMM2: out = merged @ out_w^T + out_b (out_w split done upfront)
    gemm_mma_kernel<<<dim3(4, 32), 256, GT_SMEM>>>(ah, al, owh, owl, out_b, out,
                                                   nullptr, nullptr, D_MODEL);
}

// round 16
// speedup vs baseline: 1.0738x; 1.0079x over previous
#include <cuda_runtime.h>
#include <cuda_bf16.h>
#include <math.h>
#include <stdint.h>

// Problem constants
#define NBATCH 2
#define L_SEQ 2048
#define D_MODEL 1024
#define H_HEADS 16
#define DH 64
#define QKV_STRIDE 3072
#define NH_TOT (NBATCH * H_HEADS)
#define OUT_ELEMS (NBATCH * L_SEQ * D_MODEL)
#define GK 1024
#define GKC 32
// gemm smem: 3 stages x (A 128 rows + B 256 rows) x 2 mats x 80B
#define ROW_B 80
#define SA_B (128 * ROW_B)
#define SB_B (256 * ROW_B)
#define STG_B (2 * SA_B + 2 * SB_B)
#define GT_SMEM (3 * STG_B)

#define VROW 144
#define VBUF_B (2 * 64 * VROW)          // hi+lo V chunk = 18432
#define AT_W_OFF (3 * VBUF_B)           // 55296
#define AT_SMEM (AT_W_OFF + 3 * 2 * 320 * 2)   // + wseg 3 bufs x (h,l) x 320 bf16 = 59136

// Static device scratch
__device__ float g_qkv[(size_t)NBATCH * L_SEQ * QKV_STRIDE];
__device__ float g_cpart[NH_TOT * 16 * DH];
__device__ __align__(16) __nv_bfloat16 g_ah[(size_t)4096 * 1024];
__device__ __align__(16) __nv_bfloat16 g_al[(size_t)4096 * 1024];
__device__ __align__(16) __nv_bfloat16 g_bh[(size_t)3072 * 1024];
__device__ __align__(16) __nv_bfloat16 g_bl[(size_t)3072 * 1024];
__device__ __align__(16) __nv_bfloat16 g_owh[(size_t)1024 * 1024];
__device__ __align__(16) __nv_bfloat16 g_owl[(size_t)1024 * 1024];
__device__ __align__(16) __nv_bfloat16 g_vh[(size_t)4096 * 1024];
__device__ __align__(16) __nv_bfloat16 g_vl[(size_t)4096 * 1024];
__device__ __align__(16) __nv_bfloat16 g_wnh[NH_TOT * L_SEQ];
__device__ __align__(16) __nv_bfloat16 g_wnl[NH_TOT * L_SEQ];

// ---------------------------------------------------------------------------
__device__ __forceinline__ uint32_t smem_u32(const void* p) {
    uint32_t a;
    asm("{ .reg .u64 t; cvta.to.shared.u64 t, %1; cvt.u32.u64 %0, t; }" : "=r"(a) : "l"(p));
    return a;
}

#define CP_ASYNC16(dst, src) \
    asm volatile("cp.async.cg.shared.global [%0], [%1], 16;" :: "r"(dst), "l"(src))
#define CP_ASYNC4(dst, src) \
    asm volatile("cp.async.ca.shared.global [%0], [%1], 4;" :: "r"(dst), "l"(src))
#define CP_COMMIT() asm volatile("cp.async.commit_group;" ::: "memory")
#define CP_WAIT1()  asm volatile("cp.async.wait_group 1;" ::: "memory")
#define CP_WAIT0()  asm volatile("cp.async.wait_group 0;" ::: "memory")

#define LDSM_X4(r, addr) \
    asm volatile("ldmatrix.sync.aligned.m8n8.x4.shared.b16 {%0,%1,%2,%3}, [%4];" \
        : "=r"((r)[0]), "=r"((r)[1]), "=r"((r)[2]), "=r"((r)[3]) : "r"(addr))

#define LDSM_X4_T(r, addr) \
    asm volatile("ldmatrix.sync.aligned.m8n8.x4.trans.shared.b16 {%0,%1,%2,%3}, [%4];" \
        : "=r"((r)[0]), "=r"((r)[1]), "=r"((r)[2]), "=r"((r)[3]) : "r"(addr))

#define MMA_BF16(d, a, b0, b1) \
    asm volatile("mma.sync.aligned.m16n8k16.row.col.f32.bf16.bf16.f32 " \
        "{%0,%1,%2,%3}, {%4,%5,%6,%7}, {%8,%9}, {%0,%1,%2,%3};" \
        : "+f"((d)[0]), "+f"((d)[1]), "+f"((d)[2]), "+f"((d)[3]) \
        : "r"((a)[0]), "r"((a)[1]), "r"((a)[2]), "r"((a)[3]), "r"(b0), "r"(b1))

__device__ __forceinline__ uint32_t bfpack(float a, float b) {
    __nv_bfloat16 ha = __float2bfloat16(a), hb = __float2bfloat16(b);
    return (uint32_t)__bfloat16_as_ushort(ha) | ((uint32_t)__bfloat16_as_ushort(hb) << 16);
}

__device__ __forceinline__ void split_pair(const float4* __restrict__ src,
                                           uint2* __restrict__ hi, uint2* __restrict__ lo,
                                           int i0, int i1)
{
    float4 v0 = src[i0];
    float4 v1 = src[i1];
#pragma unroll
    for (int k = 0; k < 2; k++) {
        const float4 v = k ? v1 : v0;
        const int i = k ? i1 : i0;
        __nv_bfloat16 hx = __float2bfloat16(v.x), hy = __float2bfloat16(v.y);
        __nv_bfloat16 hz = __float2bfloat16(v.z), hw = __float2bfloat16(v.w);
        uint2 h, l;
        h.x = (uint32_t)__bfloat16_as_ushort(hx) | ((uint32_t)__bfloat16_as_ushort(hy) << 16);
        h.y = (uint32_t)__bfloat16_as_ushort(hz) | ((uint32_t)__bfloat16_as_ushort(hw) << 16);
        l.x = bfpack(v.x - __bfloat162float(hx), v.y - __bfloat162float(hy));
        l.y = bfpack(v.z - __bfloat162float(hz), v.w - __bfloat162float(hw));
        hi[i] = h;
        lo[i] = l;
    }
}

// ---------------------------------------------------------------------------
// One launch splitting x, in_proj_w and out_w.
// ---------------------------------------------------------------------------
__global__ __launch_bounds__(256)
void split_all_kernel(const float4* __restrict__ x, const float4* __restrict__ in_w,
                      const float4* __restrict__ out_w)
{
    const int b = blockIdx.x;
    const int t = threadIdx.x;
    if (b < 2048) {
        const int i0 = b * 256 + t;
        split_pair(x, (uint2*)g_ah, (uint2*)g_al, i0, i0 + 2048 * 256);
    } else if (b < 3584) {
        const int i0 = (b - 2048) * 256 + t;
        split_pair(in_w, (uint2*)g_bh, (uint2*)g_bl, i0, i0 + 1536 * 256);
    } else {
        const int i0 = (b - 3584) * 256 + t;
        split_pair(out_w, (uint2*)g_owh, (uint2*)g_owl, i0, i0 + 512 * 256);
    }
}

// ---------------------------------------------------------------------------
// HMMA GEMM v3 (proven R8): CTA tile 128x256, 8 warps, warp tile 64x64.
// ---------------------------------------------------------------------------
__global__ __launch_bounds__(256, 1)
void gemm_mma_kernel(const __nv_bfloat16* __restrict__ Ah, const __nv_bfloat16* __restrict__ Al,
                     const __nv_bfloat16* __restrict__ Bh, const __nv_bfloat16* __restrict__ Bl,
                     const float* __restrict__ bias, float* __restrict__ C,
                     __nv_bfloat16* __restrict__ Vh, __nv_bfloat16* __restrict__ Vl, int N)
{
    extern __shared__ __align__(128) char smem[];
    const uint32_t sbase = smem_u32(smem);
    const int tid = threadIdx.x;
    const int lane = tid & 31, wid = tid >> 5;
    const int wm = wid >> 2, wn = wid & 3;
    const int bm = blockIdx.y << 7, bn = blockIdx.x << 8;

    auto load_stage = [&](int kc, int st_idx) {
        const uint32_t st = sbase + (uint32_t)st_idx * STG_B;
        const int koff = kc << 5;
#pragma unroll
        for (int i = 0; i < 4; i++) {
            const int idx = tid + (i << 8);
            const int mat = idx >> 9;
            const int row = (idx >> 2) & 127;
            const int c = idx & 3;
            const uint32_t so = (uint32_t)(mat * SA_B + row * ROW_B + c * 16);
            const __nv_bfloat16* src = (mat ? Al : Ah) + (size_t)(bm + row) * GK + koff + (c << 3);
            CP_ASYNC16(st + so, src);
        }
#pragma unroll
        for (int i = 0; i < 8; i++) {
            const int idx = tid + (i << 8);
            const int mat = idx >> 10;
            const int row = (idx >> 2) & 255;
            const int c = idx & 3;
            const uint32_t so = (uint32_t)(2 * SA_B + mat * SB_B + row * ROW_B + c * 16);
            const __nv_bfloat16* src = (mat ? Bl : Bh) + (size_t)(bn + row) * GK + koff + (c << 3);
            CP_ASYNC16(st + so, src);
        }
    };

    uint32_t aoff[4], boff[4];
#pragma unroll
    for (int mt = 0; mt < 4; mt++)
        aoff[mt] = (uint32_t)((wm * 64 + mt * 16 + (lane & 15)) * ROW_B + (lane >> 4) * 16);
#pragma unroll
    for (int gg = 0; gg < 4; gg++)
        boff[gg] = (uint32_t)((wn * 64 + gg * 16 + ((lane >> 4) & 1) * 8 + (lane & 7)) * ROW_B
                              + ((lane >> 3) & 1) * 16);

    float acc[4][8][4];
#pragma unroll
    for (int i = 0; i < 4; i++)
#pragma unroll
        for (int j = 0; j < 8; j++)
#pragma unroll
            for (int r = 0; r < 4; r++) acc[i][j][r] = 0.f;

    load_stage(0, 0); CP_COMMIT();
    load_stage(1, 1); CP_COMMIT();

    int s = 0;
    for (int kc = 0; kc < GKC; kc++) {
        CP_WAIT1();
        __syncthreads();
        if (kc + 2 < GKC) load_stage(kc + 2, (kc + 2) % 3);
        CP_COMMIT();

        const uint32_t st = sbase + (uint32_t)s * STG_B;
#pragma unroll
        for (int ks = 0; ks < 2; ks++) {
            const uint32_t ko = (uint32_t)(ks * 32);
            uint32_t ah[4][4], al[4][4];
#pragma unroll
            for (int mt = 0; mt < 4; mt++) {
                LDSM_X4(ah[mt], st + aoff[mt] + ko);
                LDSM_X4(al[mt], st + SA_B + aoff[mt] + ko);
            }
#pragma unroll
            for (int gg = 0; gg < 4; gg++) {
                uint32_t bh4[4], bl4[4];
                LDSM_X4(bh4, st + 2 * SA_B + boff[gg] + ko);
                LDSM_X4(bl4, st + 2 * SA_B + SB_B + boff[gg] + ko);
#pragma unroll
                for (int mt = 0; mt < 4; mt++) {
                    MMA_BF16(acc[mt][gg * 2],     ah[mt], bh4[0], bh4[1]);
                    MMA_BF16(acc[mt][gg * 2 + 1], ah[mt], bh4[2], bh4[3]);
                }
#pragma unroll
                for (int mt = 0; mt < 4; mt++) {
                    MMA_BF16(acc[mt][gg * 2],     ah[mt], bl4[0], bl4[1]);
                    MMA_BF16(acc[mt][gg * 2 + 1], ah[mt], bl4[2], bl4[3]);
                }
#pragma unroll
                for (int mt = 0; mt < 4; mt++) {
                    MMA_BF16(acc[mt][gg * 2],     al[mt], bh4[0], bh4[1]);
                    MMA_BF16(acc[mt][gg * 2 + 1], al[mt], bh4[2], bh4[3]);
                }
            }
        }
        s++; if (s == 3) s = 0;
    }

    const bool vsplit = (Vh != nullptr) && (bn >= 2048);
#pragma unroll
    for (int mt = 0; mt < 4; mt++) {
        const int r0 = bm + wm * 64 + mt * 16 + (lane >> 2);
#pragma unroll
        for (int j = 0; j < 8; j++) {
            const int colg = bn + wn * 64 + (j >> 1) * 16 + (j & 1) * 8 + (lane & 3) * 2;
            const float b0 = bias[colg], b1 = bias[colg + 1];
            const float v00 = acc[mt][j][0] + b0, v01 = acc[mt][j][1] + b1;
            const float v10 = acc[mt][j][2] + b0, v11 = acc[mt][j][3] + b1;
            if (!vsplit) {
                *(float2*)(C + (size_t)r0 * N + colg) = make_float2(v00, v01);
                *(float2*)(C + (size_t)(r0 + 8) * N + colg) = make_float2(v10, v11);
            } else {
                const int cv = colg - 2048;
                uint32_t* vh32 = (uint32_t*)Vh;
                uint32_t* vl32 = (uint32_t*)Vl;
                {
                    __nv_bfloat16 h0 = __float2bfloat16(v00), h1 = __float2bfloat16(v01);
                    uint32_t ph = (uint32_t)__bfloat16_as_ushort(h0) |
                                  ((uint32_t)__bfloat16_as_ushort(h1) << 16);
                    uint32_t pl = bfpack(v00 - __bfloat162float(h0), v01 - __bfloat162float(h1));
                    vh32[((size_t)r0 * 1024 + cv) >> 1] = ph;
                    vl32[((size_t)r0 * 1024 + cv) >> 1] = pl;
                }
                {
                    __nv_bfloat16 h0 = __float2bfloat16(v10), h1 = __float2bfloat16(v11);
                    uint32_t ph = (uint32_t)__bfloat16_as_ushort(h0) |
                                  ((uint32_t)__bfloat16_as_ushort(h1) << 16);
                    uint32_t pl = bfpack(v10 - __bfloat162float(h0), v11 - __bfloat162float(h1));
                    vh32[((size_t)(r0 + 8) * 1024 + cv) >> 1] = ph;
                    vl32[((size_t)(r0 + 8) * 1024 + cv) >> 1] = pl;
                }
            }
        }
    }
}

// ---------------------------------------------------------------------------
// conv -> GELU -> LN -> partial mean over a 128-t chunk. Grid (16, 32).
// ---------------------------------------------------------------------------
__global__ __launch_bounds__(256)
void conv_part_kernel(const float* __restrict__ conv_w, const float* __restrict__ conv_b,
                      const float* __restrict__ ln_g, const float* __restrict__ ln_b)
{
    const int chunk = blockIdx.x;
    const int nh = blockIdx.y;
    const int n = nh >> 4, h = nh & 15;
    const int tid = threadIdx.x;
    const int w = tid >> 5, lane = tid & 31;
    const int d0 = lane, d1 = lane + 32;
    const float* qbase = g_qkv + (size_t)n * L_SEQ * QKV_STRIDE + h * DH;

    const float cw00 = conv_w[d0 * 3 + 0], cw01 = conv_w[d0 * 3 + 1], cw02 = conv_w[d0 * 3 + 2];
    const float cw10 = conv_w[d1 * 3 + 0], cw11 = conv_w[d1 * 3 + 1], cw12 = conv_w[d1 * 3 + 2];
    const float cb0 = conv_b[d0], cb1 = conv_b[d1];
    const float lg0 = ln_g[d0], lb0 = ln_b[d0];
    const float lg1 = ln_g[d1], lb1 = ln_b[d1];

    float p0 = 0.f, p1 = 0.f;
#pragma unroll 4
    for (int i = 0; i < 16; i++) {
        const int t = chunk * 128 + (w << 4) + i;
        float c0 = cb0, c1 = cb1;
        {
            const float* r = qbase + (size_t)t * QKV_STRIDE;
            c0 = fmaf(r[d0], cw02, c0); c1 = fmaf(r[d1], cw12, c1);
        }
        if (t >= 1) {
            const float* r = qbase + (size_t)(t - 1) * QKV_STRIDE;
            c0 = fmaf(r[d0], cw01, c0); c1 = fmaf(r[d1], cw11, c1);
        }
        if (t >= 2) {
            const float* r = qbase + (size_t)(t - 2) * QKV_STRIDE;
            c0 = fmaf(r[d0], cw00, c0); c1 = fmaf(r[d1], cw10, c1);
        }
        float g0 = 0.5f * c0 * (1.f + erff(c0 * 0.70710678118654752f));
        float g1 = 0.5f * c1 * (1.f + erff(c1 * 0.70710678118654752f));
        float sv = g0 + g1, sq = g0 * g0 + g1 * g1;
#pragma unroll
        for (int o = 16; o; o >>= 1) {
            sv += __shfl_xor_sync(0xffffffffu, sv, o);
            sq += __shfl_xor_sync(0xffffffffu, sq, o);
        }
        float mu = sv * (1.f / 64.f);
        float var = sq * (1.f / 64.f) - mu * mu;
        float rs = rsqrtf(var + 1e-5f);
        p0 += (g0 - mu) * rs * lg0 + lb0;
        p1 += (g1 - mu) * rs * lg1 + lb1;
    }

    __shared__ float part[8][64];
    part[w][d0] = p0;
    part[w][d1] = p1;
    __syncthreads();
    if (tid < 64) {
        float sv = 0.f;
#pragma unroll
        for (int i = 0; i < 8; i++) sv += part[i][tid];
        g_cpart[(nh * 16 + chunk) * 64 + tid] = sv;
    }
}

// ---------------------------------------------------------------------------
// Reduce conv partials -> q_rel -> Wk -> L1 norm -> Wn bf16 split. (merged)
// ---------------------------------------------------------------------------
__global__ __launch_bounds__(256)
void wk_kernel()
{
    const int nh = blockIdx.x;
    const int n = nh >> 4, h = nh & 15;
    const int tid = threadIdx.x;
    __shared__ float4 qs4[16];
    if (tid < 64) {
        float sv = 0.f;
#pragma unroll
        for (int i = 0; i < 16; i++) sv += g_cpart[(nh * 16 + i) * 64 + tid];
        ((float*)qs4)[tid] = sv * (0.125f / 2048.f);
    }
    __syncthreads();

    const float* kbase = g_qkv + (size_t)n * L_SEQ * QKV_STRIDE + D_MODEL + h * DH;
    float wk[8];
    float la = 0.f;
#pragma unroll
    for (int i = 0; i < 8; i++) {
        int l = tid + i * 256;
        const float4* kr = (const float4*)(kbase + (size_t)l * QKV_STRIDE);
        float a = 0.f;
#pragma unroll
        for (int d4 = 0; d4 < 16; d4++) {
            float4 kv = kr[d4]; float4 q = qs4[d4];
            a = fmaf(q.x, kv.x, a); a = fmaf(q.y, kv.y, a);
            a = fmaf(q.z, kv.z, a); a = fmaf(q.w, kv.w, a);
        }
        wk[i] = a;
        la += fabsf(a);
    }
    __shared__ float red[256];
    red[tid] = la;
    __syncthreads();
    for (int o = 128; o; o >>= 1) {
        if (tid < o) red[tid] += red[tid + o];
        __syncthreads();
    }
    const float scale = 1.f / (red[0] + 1e-6f);
#pragma unroll
    for (int i = 0; i < 8; i++) {
        const float wv = wk[i] * scale;
        __nv_bfloat16 hh = __float2bfloat16(wv);
        g_wnh[nh * L_SEQ + tid + i * 256] = hh;
        g_wnl[nh * L_SEQ + tid + i * 256] = __float2bfloat16(wv - __bfloat162float(hh));
    }
}

// ---------------------------------------------------------------------------
// Toeplitz attention via HMMA v5: R12 warp shape + GEMM-style 3-stage
// pipeline with ONE sync per chunk (dynamic smem, 59 KB). 8 warps x 32
// t-rows (2 m-tiles each), 256 t-rows per CTA, heavy-first, diagonal skip.
// ---------------------------------------------------------------------------
__global__ __launch_bounds__(256, 1)
void attn_mma_kernel()
{
    extern __shared__ __align__(16) char asm_[];
    const uint32_t vbase = smem_u32(asm_);
    __nv_bfloat16* wseg = (__nv_bfloat16*)(asm_ + AT_W_OFF);   // [buf*2+hl][320]

    const int bid = blockIdx.x;
    const int g8 = 7 - (bid >> 5);
    const int nh = bid & 31;
    const int n = nh >> 4, h = nh & 15;
    const int tid = threadIdx.x;
    const int lane = tid & 31, w = tid >> 5;
    const int t_base = g8 << 8;
    const int C = 4 * g8 + 4;

    const __nv_bfloat16* wnh = g_wnh + nh * L_SEQ;
    const __nv_bfloat16* wnl = g_wnl + nh * L_SEQ;
    const __nv_bfloat16 zero = __float2bfloat16(0.f);

    auto load_chunk = [&](int c, int buf) {
        // Wn segment (320 entries, hi+lo)
        const int base = t_base - (c << 6) - 63;
        __nv_bfloat16* wh = wseg + (buf * 2) * 320;
        __nv_bfloat16* wl = wh + 320;
        {
            const int j = tid;
            const int lag = base + j;
            wh[j] = (lag >= 0) ? wnh[lag] : zero;
            wl[j] = (lag >= 0) ? wnl[lag] : zero;
        }
        if (tid < 64) {
            const int j = 256 + tid;
            const int lag = base + j;
            wh[j] = (lag >= 0) ? wnh[lag] : zero;
            wl[j] = (lag >= 0) ? wnl[lag] : zero;
        }
        // V chunk (hi+lo) via cp.async
        const uint32_t vb = vbase + (uint32_t)buf * VBUF_B;
#pragma unroll
        for (int i = 0; i < 2; i++) {
            const int idx = tid + (i << 8);
            const int row = idx >> 3, ch = idx & 7;
            const size_t ga = (size_t)(n * L_SEQ + (c << 6) + row) * 1024 + h * DH + (ch << 3);
            const uint32_t so = (uint32_t)(row * VROW + (ch << 4));
            CP_ASYNC16(vb + so,             g_vh + ga);
            CP_ASYNC16(vb + so + 64 * VROW, g_vl + ga);
        }
    };

    float acc[2][8][4];
#pragma unroll
    for (int m = 0; m < 2; m++)
#pragma unroll
        for (int i = 0; i < 8; i++)
#pragma unroll
            for (int j = 0; j < 4; j++) acc[m][i][j] = 0.f;

    load_chunk(0, 0); CP_COMMIT();
    if (C > 1) load_chunk(1, 1);
    CP_COMMIT();

    const int r0 = lane >> 2;
    const int c0 = (lane & 3) << 1;
    const uint32_t lrow = (uint32_t)(lane & 15);
    const uint32_t lcol = (uint32_t)((lane >> 4) << 4);

    int s = 0;
    for (int c = 0; c < C; c++) {
        CP_WAIT1();
        __syncthreads();
        if (c + 2 < C) load_chunk(c + 2, (c + 2) % 3);
        CP_COMMIT();

        if (t_base + (w << 5) + 31 >= (c << 6)) {
            const __nv_bfloat16* wh = wseg + (s * 2) * 320;
            const __nv_bfloat16* wl = wh + 320;
            const uint32_t vh_s = vbase + (uint32_t)s * VBUF_B;
            const uint32_t vl_s = vh_s + 64 * VROW;

#pragma unroll
            for (int ks = 0; ks < 4; ks++) {
                const int jbw = 63 + (w << 5) + r0 - (ks << 4) - c0;
                uint32_t hA = (uint32_t)__bfloat16_as_ushort(wh[jbw - 8]) |
                              ((uint32_t)__bfloat16_as_ushort(wh[jbw - 9]) << 16);
                uint32_t hB = (uint32_t)__bfloat16_as_ushort(wh[jbw]) |
                              ((uint32_t)__bfloat16_as_ushort(wh[jbw - 1]) << 16);
                uint32_t hCq = (uint32_t)__bfloat16_as_ushort(wh[jbw + 8]) |
                              ((uint32_t)__bfloat16_as_ushort(wh[jbw + 7]) << 16);
                uint32_t hD = (uint32_t)__bfloat16_as_ushort(wh[jbw + 16]) |
                              ((uint32_t)__bfloat16_as_ushort(wh[jbw + 15]) << 16);
                uint32_t hE = (uint32_t)__bfloat16_as_ushort(wh[jbw + 24]) |
                              ((uint32_t)__bfloat16_as_ushort(wh[jbw + 23]) << 16);
                uint32_t lA = (uint32_t)__bfloat16_as_ushort(wl[jbw - 8]) |
                              ((uint32_t)__bfloat16_as_ushort(wl[jbw - 9]) << 16);
                uint32_t lB = (uint32_t)__bfloat16_as_ushort(wl[jbw]) |
                              ((uint32_t)__bfloat16_as_ushort(wl[jbw - 1]) << 16);
                uint32_t lCq = (uint32_t)__bfloat16_as_ushort(wl[jbw + 8]) |
                              ((uint32_t)__bfloat16_as_ushort(wl[jbw + 7]) << 16);
                uint32_t lD = (uint32_t)__bfloat16_as_ushort(wl[jbw + 16]) |
                              ((uint32_t)__bfloat16_as_ushort(wl[jbw + 15]) << 16);
                uint32_t lE = (uint32_t)__bfloat16_as_ushort(wl[jbw + 24]) |
                              ((uint32_t)__bfloat16_as_ushort(wl[jbw + 23]) << 16);
                uint32_t a0h[4] = {hB, hCq, hA, hB};
                uint32_t a1h[4] = {hD, hE, hCq, hD};
                uint32_t a0l[4] = {lB, lCq, lA, lB};
                uint32_t a1l[4] = {lD, lE, lCq, lD};

                const uint32_t radd = (uint32_t)((ks * 16 + lrow) * VROW) + lcol;
#pragma unroll
                for (int gg = 0; gg < 4; gg++) {
                    uint32_t bh4[4], bl4[4];
                    const uint32_t ga = radd + (uint32_t)(gg << 5);
                    LDSM_X4_T(bh4, vh_s + ga);
                    LDSM_X4_T(bl4, vl_s + ga);
                    MMA_BF16(acc[0][gg * 2],     a0h, bh4[0], bh4[1]);
                    MMA_BF16(acc[0][gg * 2 + 1], a0h, bh4[2], bh4[3]);
                    MMA_BF16(acc[1][gg * 2],     a1h, bh4[0], bh4[1]);
                    MMA_BF16(acc[1][gg * 2 + 1], a1h, bh4[2], bh4[3]);
                    MMA_BF16(acc[0][gg * 2],     a0h, bl4[0], bl4[1]);
                    MMA_BF16(acc[0][gg * 2 + 1], a0h, bl4[2], bl4[3]);
                    MMA_BF16(acc[1][gg * 2],     a1l, bh4[0], bh4[1]);
                    MMA_BF16(acc[1][gg * 2 + 1], a1l, bh4[2], bh4[3]);
                    MMA_BF16(acc[0][gg * 2],     a0l, bh4[0], bh4[1]);
                    MMA_BF16(acc[0][gg * 2 + 1], a0l, bh4[2], bh4[3]);
                    MMA_BF16(acc[1][gg * 2],     a1h, bl4[0], bl4[1]);
                    MMA_BF16(acc[1][gg * 2 + 1], a1h, bl4[2], bl4[3]);
                }
            }
        }
        s++; if (s == 3) s = 0;
    }

    uint32_t* mh32 = (uint32_t*)g_ah;
    uint32_t* ml32 = (uint32_t*)g_al;
#pragma unroll
    for (int mt = 0; mt < 2; mt++) {
        const size_t rA = (size_t)(n * L_SEQ + t_base + (w << 5) + (mt << 4) + r0);
#pragma unroll
        for (int nb = 0; nb < 8; nb++) {
            const int col = h * DH + nb * 8 + c0;
            {
                float v0 = acc[mt][nb][0], v1 = acc[mt][nb][1];
                __nv_bfloat16 h0 = __float2bfloat16(v0), h1 = __float2bfloat16(v1);
                uint32_t ph = (uint32_t)__bfloat16_as_ushort(h0) |
                              ((uint32_t)__bfloat16_as_ushort(h1) << 16);
                uint32_t pl = bfpack(v0 - __bfloat162float(h0), v1 - __bfloat162float(h1));
                mh32[(rA * 1024 + col) >> 1] = ph;
                ml32[(rA * 1024 + col) >> 1] = pl;
            }
            {
                float v0 = acc[mt][nb][2], v1 = acc[mt][nb][3];
                __nv_bfloat16 h0 = __float2bfloat16(v0), h1 = __float2bfloat16(v1);
                uint32_t ph = (uint32_t)__bfloat16_as_ushort(h0) |
                              ((uint32_t)__bfloat16_as_ushort(h1) << 16);
                uint32_t pl = bfpack(v0 - __bfloat162float(h0), v1 - __bfloat162float(h1));
                mh32[((rA + 8) * 1024 + col) >> 1] = ph;
                ml32[((rA + 8) * 1024 + col) >> 1] = pl;
            }
        }
    }
}

__global__ void fill_kernel(float* p, int nfill, float v)
{
    int i = blockIdx.x * blockDim.x + threadIdx.x;
    if (i < nfill) p[i] = v;
}

// ---------------------------------------------------------------------------
extern "C" void kernel_launch(void* const* d_in, const int* in_sizes, int n_in,
                              void* d_out, int out_size)
{
    const float* x      = (const float*)d_in[0];
    const float* in_w   = (const float*)d_in[1];
    const float* in_b   = (const float*)d_in[2];
    const float* conv_w = (const float*)d_in[3];
    const float* conv_b = (const float*)d_in[4];
    const float* ln_g   = (const float*)d_in[5];
    const float* ln_b   = (const float*)d_in[6];
    const float* out_w  = (const float*)d_in[7];
    const float* out_b  = (const float*)d_in[8];
    float* out = (float*)d_out;

    void* p;
    cudaGetSymbolAddress(&p, g_qkv);    float* qkv = (float*)p;
    cudaGetSymbolAddress(&p, g_ah);     __nv_bfloat16* ah = (__nv_bfloat16*)p;
    cudaGetSymbolAddress(&p, g_al);     __nv_bfloat16* al = (__nv_bfloat16*)p;
    cudaGetSymbolAddress(&p, g_bh);     __nv_bfloat16* bh = (__nv_bfloat16*)p;
    cudaGetSymbolAddress(&p, g_bl);     __nv_bfloat16* bl = (__nv_bfloat16*)p;
    cudaGetSymbolAddress(&p, g_owh);    __nv_bfloat16* owh = (__nv_bfloat16*)p;
    cudaGetSymbolAddress(&p, g_owl);    __nv_bfloat16* owl = (__nv_bfloat16*)p;
    cudaGetSymbolAddress(&p, g_vh);     __nv_bfloat16* vh = (__nv_bfloat16*)p;
    cudaGetSymbolAddress(&p, g_vl);     __nv_bfloat16* vl = (__nv_bfloat16*)p;

    cudaFuncSetAttribute(gemm_mma_kernel, cudaFuncAttributeMaxDynamicSharedMemorySize, GT_SMEM);
    cudaFuncSetAttribute(attn_mma_kernel, cudaFuncAttributeMaxDynamicSharedMemorySize, AT_SMEM);

    // mock attention weights (independent — run first)
    int nmock = out_size - OUT_ELEMS;
    if (nmock > 0)
        fill_kernel<<<(nmock + 255) / 256, 256>>>(out + OUT_ELEMS, nmock, 1.0f / (float)L_SEQ);

    // all input splits in one launch: x, in_w, out_w
    split_all_kernel<<<4096, 256>>>((const float4*)x, (const float4*)in_w, (const float4*)out_w);

    // GEMM1 (merged): q,k cols -> qkv fp32; V cols -> bf16 hi/lo split (fused)
    gemm_mma_kernel<<<dim3(12, 32), 256, GT_SMEM>>>(ah, al, bh, bl, in_b, qkv, vh, vl, QKV_STRIDE);

    // conv -> gelu -> LN -> partial mean
    conv_part_kernel<<<dim3(16, NH_TOT), 256>>>(conv_w, conv_b, ln_g, ln_b);

    // reduce + Wk -> Wn (bf16 split), merged
    wk_kernel<<<NH_TOT, 256>>>();

    // causal Toeplitz attention (HMMA, 3-stage pipeline, one sync per chunk)
    attn_mma_kernel<<<256, 256, AT_SMEM>>>();

    // GEMM2: out = merged @ out_w^T + out_b
    gemm_mma_kernel<<<dim3(4, 32), 256, GT_SMEM>>>(ah, al, owh, owl, out_b, out,
                                                   nullptr, nullptr, D_MODEL);
}